// round 8
// baseline (speedup 1.0000x reference)
#include <cuda_runtime.h>
#include <cuda_bf16.h>
#include <cstdint>

#define NPOST 100000
#define NUSER 50000
#define NENT  20000
#define NEDGE_TOT 1550000
#define NSRC_TOT 400000     // sum of per-relation src node counts
#define NDST_TOT 420000     // sum of per-relation dst node counts
#define ACC_TOT  10880000   // (NPOST+NUSER+NENT)*64

// ---------------- static device scratch ----------------
__device__ float g_h_post[NPOST * 64];
__device__ float g_h_user[NUSER * 64];
__device__ float g_h_ent [NENT  * 64];
__device__ float g_acc_post[NPOST * 64];
__device__ float g_acc_user[NUSER * 64];
__device__ float g_acc_ent [NENT  * 64];
__device__ float g_hs[51200000];        // concat per-relation hs [N_src][128]
__device__ float2 g_al_s[NSRC_TOT];
__device__ float2 g_al_d[NDST_TOT];
__device__ unsigned int g_m[NDST_TOT * 2];  // encoded float max per (dst,head)
__device__ float        g_ss[NDST_TOT * 2]; // softmax denom -> inverted in place
__device__ float2 g_p[NEDGE_TOT];           // unnormalized softmax numerators
__device__ float g_u[3072];             // folded attention vectors [l][r][side][h][64]

// ---------------- constant tables ----------------
__constant__ int c_EPFX[7]  = {0, 100000, 300000, 500000, 900000, 1300000, 1550000};
__constant__ int c_SOFF[6]  = {0, 50000, 100000, 200000, 250000, 300000};
__constant__ int c_DOFF[6]  = {0, 100000, 200000, 220000, 270000, 320000};
__constant__ int c_HSOFF[6] = {0, 6400000, 12800000, 25600000, 32000000, 38400000};
__constant__ int c_ALPFX[13] = {0, 50000, 100000, 200000, 250000, 300000, 400000,
                                500000, 600000, 620000, 670000, 720000, 820000};
// hs dispatch: blocks of 128 nodes per relation: {391,391,782,391,391,782}
__constant__ int c_HSBLK[7] = {0, 391, 782, 1564, 1955, 2346, 3128};
__constant__ int c_NSRC[6]  = {50000, 50000, 100000, 50000, 50000, 100000};

struct EdgeParams { const int* src[6]; const int* dst[6]; };

// ---------------- helpers ----------------
__device__ __forceinline__ const float* src_x(int rel) {
    return (rel == 2 || rel == 5) ? g_h_post : g_h_user;
}
__device__ __forceinline__ const float* dst_x(int rel) {
    if (rel == 2) return g_h_ent;
    if (rel == 3 || rel == 4) return g_h_user;
    return g_h_post;
}
__device__ __forceinline__ float* out_acc(int rel) {
    if (rel == 2) return g_acc_ent;
    if (rel == 3 || rel == 4) return g_acc_user;
    return g_acc_post;
}
__device__ __forceinline__ float lrelu(float x) { return x > 0.0f ? x : 0.2f * x; }
__device__ __forceinline__ unsigned int encf(float f) {
    unsigned int u = __float_as_uint(f);
    return (u & 0x80000000u) ? ~u : (u | 0x80000000u);
}
__device__ __forceinline__ float decf(unsigned int u) {
    return (u & 0x80000000u) ? __uint_as_float(u & 0x7fffffffu) : __uint_as_float(~u);
}
__device__ __forceinline__ int edge_rel(int gid) {
    int rel = 0;
#pragma unroll
    for (int r = 1; r < 6; r++) if (gid >= c_EPFX[r]) rel = r;
    return rel;
}

// ---------------- fat-tile GEMM: Y[n][m] = sum_k X[n][k]*W[m][k] (+ B[m]) ----------------
// Block = 256 threads handles 128 nodes x M cols; per-thread 8 x TM register tile.
// Inner loop: 64 (M=128) / 32 (M=64) FFMA per 4/3 LDS.128. K % 32 == 0.
template <int K, int M>
__device__ __forceinline__ void gemm_fat(const float* __restrict__ X,
                                         const float* __restrict__ W,
                                         const float* __restrict__ B,
                                         float* __restrict__ Y, int N, int n0)
{
    constexpr int TM  = M / 16;        // cols per thread (4 or 8)
    constexpr int TPR = 256 / M;       // threads per W row (4 or 2)
    constexpr int LW  = 32 / TPR;      // k's per thread for W staging (8 or 16)
    __shared__ float Xs[32][128];
    __shared__ float Ws[32][M + 4];

    const int t  = threadIdx.x;
    const int tx = t & 15, ty = t >> 4;
    const int xn = t >> 1, xk0 = (t & 1) * 16;   // 2 threads per node, 16 k's each
    const int wm = t / TPR, wk0 = (t % TPR) * LW;

    float acc[8][TM];
#pragma unroll
    for (int i = 0; i < 8; i++)
#pragma unroll
        for (int j = 0; j < TM; j++) acc[i][j] = 0.0f;

    const bool xok = (n0 + xn) < N;

    for (int k0 = 0; k0 < K; k0 += 32) {
        // fetch to regs
        float4 xr[4];
#pragma unroll
        for (int j = 0; j < 4; j++) xr[j] = make_float4(0.f, 0.f, 0.f, 0.f);
        if (xok) {
            const float4* g = reinterpret_cast<const float4*>(
                X + (size_t)(n0 + xn) * K + k0 + xk0);
#pragma unroll
            for (int j = 0; j < 4; j++) xr[j] = g[j];
        }
        float4 wr[LW / 4];
        {
            const float4* g = reinterpret_cast<const float4*>(
                W + (size_t)wm * K + k0 + wk0);
#pragma unroll
            for (int j = 0; j < LW / 4; j++) wr[j] = g[j];
        }
        __syncthreads();   // previous tile fully consumed
#pragma unroll
        for (int j = 0; j < 4; j++) {
            Xs[xk0 + 4 * j + 0][xn] = xr[j].x;
            Xs[xk0 + 4 * j + 1][xn] = xr[j].y;
            Xs[xk0 + 4 * j + 2][xn] = xr[j].z;
            Xs[xk0 + 4 * j + 3][xn] = xr[j].w;
        }
#pragma unroll
        for (int j = 0; j < LW / 4; j++) {
            Ws[wk0 + 4 * j + 0][wm] = wr[j].x;
            Ws[wk0 + 4 * j + 1][wm] = wr[j].y;
            Ws[wk0 + 4 * j + 2][wm] = wr[j].z;
            Ws[wk0 + 4 * j + 3][wm] = wr[j].w;
        }
        __syncthreads();

#pragma unroll
        for (int kk = 0; kk < 32; kk++) {
            float4 xa = *reinterpret_cast<const float4*>(&Xs[kk][ty * 8]);
            float4 xb = *reinterpret_cast<const float4*>(&Xs[kk][ty * 8 + 4]);
            float xv[8] = {xa.x, xa.y, xa.z, xa.w, xb.x, xb.y, xb.z, xb.w};
            float wv[TM];
#pragma unroll
            for (int j = 0; j < TM; j += 4) {
                float4 w4 = *reinterpret_cast<const float4*>(&Ws[kk][tx * TM + j]);
                wv[j] = w4.x; wv[j + 1] = w4.y; wv[j + 2] = w4.z; wv[j + 3] = w4.w;
            }
#pragma unroll
            for (int i = 0; i < 8; i++)
#pragma unroll
                for (int j = 0; j < TM; j++)
                    acc[i][j] = fmaf(xv[i], wv[j], acc[i][j]);
        }
        __syncthreads();
    }

    float bj[TM];
#pragma unroll
    for (int j = 0; j < TM; j++) bj[j] = B ? B[tx * TM + j] : 0.0f;
#pragma unroll
    for (int i = 0; i < 8; i++) {
        int n = n0 + ty * 8 + i;
        if (n < N) {
#pragma unroll
            for (int j = 0; j < TM; j += 4) {
                float4 v;
                v.x = acc[i][j + 0] + bj[j + 0];
                v.y = acc[i][j + 1] + bj[j + 1];
                v.z = acc[i][j + 2] + bj[j + 2];
                v.w = acc[i][j + 3] + bj[j + 3];
                *reinterpret_cast<float4*>(Y + (size_t)n * M + tx * TM + j) = v;
            }
        }
    }
}

// ---------------- kernels ----------------
__global__ void __launch_bounds__(256) proj_post_k(const float* X, const float* W, const float* B) {
    gemm_fat<768, 64>(X, W, B, g_h_post, NPOST, blockIdx.x * 128);
}
__global__ void __launch_bounds__(256) proj_user_k(const float* X, const float* W, const float* B) {
    gemm_fat<32, 64>(X, W, B, g_h_user, NUSER, blockIdx.x * 128);
}
__global__ void __launch_bounds__(256) proj_ent_k(const float* X, const float* W, const float* B) {
    gemm_fat<64, 64>(X, W, B, g_h_ent, NENT, blockIdx.x * 128);
}
// hs for all 6 relations in one launch: hs = x_src @ W_src[l,rel].T : [N_src, 128]
__global__ void __launch_bounds__(256) hs_all_k(const float* __restrict__ Wsrc, int l) {
    int b = blockIdx.x;
    int rel = 0;
#pragma unroll
    for (int r = 1; r < 6; r++) if (b >= c_HSBLK[r]) rel = r;
    gemm_fat<64, 128>(src_x(rel), Wsrc + ((size_t)l * 6 + rel) * 8192, nullptr,
                      g_hs + c_HSOFF[rel], c_NSRC[rel], (b - c_HSBLK[rel]) * 128);
}

// folded attention vectors: u[l][r][side][h][k] = sum_c a[l][r][h][c] * W[l][r][h*64+c][k]
__global__ void u_k(const float* __restrict__ Ws, const float* __restrict__ Wd,
                    const float* __restrict__ as_, const float* __restrict__ ad_) {
    int id = blockIdx.x * 256 + threadIdx.x;
    if (id >= 3072) return;
    int k = id & 63, h = (id >> 6) & 1, side = (id >> 7) & 1, rl = id >> 8;
    const float* a = (side ? ad_ : as_) + (size_t)rl * 128 + h * 64;
    const float* W = (side ? Wd : Ws) + (size_t)rl * 8192 + (size_t)h * 64 * 64;
    float u = 0.0f;
#pragma unroll 8
    for (int c = 0; c < 64; c++) u = fmaf(a[c], W[c * 64 + k], u);
    g_u[id] = u;
}

// attention scalars per node for all 12 (relation,side) tasks
__global__ void __launch_bounds__(256) al_k(int l) {
    int gid = blockIdx.x * 256 + threadIdx.x;
    if (gid >= 820000) return;
    int t = 0;
#pragma unroll
    for (int i = 1; i < 12; i++) if (gid >= c_ALPFX[i]) t = i;
    int n = gid - c_ALPFX[t];
    int side = (t >= 6) ? 1 : 0;
    int rel = side ? t - 6 : t;
    const float* xr = (side ? dst_x(rel) : src_x(rel)) + (size_t)n * 64;
    const float4* x4 = reinterpret_cast<const float4*>(xr);
    const float4* u4 = reinterpret_cast<const float4*>(
        g_u + ((size_t)(l * 6 + rel) * 2 + side) * 128);
    float a0 = 0.0f, a1 = 0.0f;
#pragma unroll
    for (int k = 0; k < 16; k++) {
        float4 xv = x4[k], u0 = u4[k], u1 = u4[16 + k];
        a0 = fmaf(xv.x, u0.x, fmaf(xv.y, u0.y, fmaf(xv.z, u0.z, fmaf(xv.w, u0.w, a0))));
        a1 = fmaf(xv.x, u1.x, fmaf(xv.y, u1.y, fmaf(xv.z, u1.z, fmaf(xv.w, u1.w, a1))));
    }
    float2 r; r.x = a0; r.y = a1;
    if (side) g_al_d[c_DOFF[rel] + n] = r;
    else      g_al_s[c_SOFF[rel] + n] = r;
}

// fused: zero softmax stats + init accumulators with summed gat biases
__global__ void reset_k(const float* __restrict__ gb, int l) {
    int gid = blockIdx.x * 256 + threadIdx.x;
    if (gid >= ACC_TOT) return;
    if (gid < NDST_TOT * 2) {
        g_m[gid] = 0u;      // encoded floor (< any finite float)
        g_ss[gid] = 0.0f;
    }
    int c = gid & 63;
    const float* b = gb + l * 384;  // [6][64]
    if (gid < NPOST * 64)
        g_acc_post[gid] = b[0 * 64 + c] + b[1 * 64 + c] + b[5 * 64 + c];
    else if (gid < (NPOST + NUSER) * 64)
        g_acc_user[gid - NPOST * 64] = b[3 * 64 + c] + b[4 * 64 + c];
    else
        g_acc_ent[gid - (NPOST + NUSER) * 64] = b[2 * 64 + c];
}

__global__ void __launch_bounds__(256) edge_max_k(EdgeParams p) {
    int gid = blockIdx.x * 256 + threadIdx.x;
    if (gid >= NEDGE_TOT) return;
    int rel = edge_rel(gid);
    int e = gid - c_EPFX[rel];
    int s = p.src[rel][e], d = p.dst[rel][e];
    float2 as = g_al_s[c_SOFF[rel] + s];
    float2 ad = g_al_d[c_DOFF[rel] + d];
    float e0 = lrelu(as.x + ad.x);
    float e1 = lrelu(as.y + ad.y);
    int di = (c_DOFF[rel] + d) * 2;
    atomicMax(&g_m[di + 0], encf(e0));
    atomicMax(&g_m[di + 1], encf(e1));
}

// exp(e - m), accumulate denominator, and stash numerator per edge
__global__ void __launch_bounds__(256) edge_sum_k(EdgeParams p) {
    int gid = blockIdx.x * 256 + threadIdx.x;
    if (gid >= NEDGE_TOT) return;
    int rel = edge_rel(gid);
    int e = gid - c_EPFX[rel];
    int s = p.src[rel][e], d = p.dst[rel][e];
    float2 as = g_al_s[c_SOFF[rel] + s];
    float2 ad = g_al_d[c_DOFF[rel] + d];
    float e0 = lrelu(as.x + ad.x);
    float e1 = lrelu(as.y + ad.y);
    int di = (c_DOFF[rel] + d) * 2;
    float p0 = __expf(e0 - decf(g_m[di + 0]));
    float p1 = __expf(e1 - decf(g_m[di + 1]));
    atomicAdd(&g_ss[di + 0], p0);
    atomicAdd(&g_ss[di + 1], p1);
    float2 pr; pr.x = p0; pr.y = p1;
    g_p[gid] = pr;
}

// invert denominators in place, folding in head-mean 0.5x
__global__ void inv_k() {
    int gid = blockIdx.x * 256 + threadIdx.x;
    if (gid >= NDST_TOT * 2) return;
    g_ss[gid] = 0.5f / (g_ss[gid] + 1e-16f);
}

// 16 threads per edge, 4 channels each; single float4 vector atomic per thread
__global__ void __launch_bounds__(256) edge_msg_k(EdgeParams p) {
    int gid = blockIdx.x * 256 + threadIdx.x;
    if (gid >= NEDGE_TOT * 16) return;
    int e = gid >> 4, c0 = (gid & 15) << 2;
    int rel = edge_rel(e);
    int eloc = e - c_EPFX[rel];
    int s = p.src[rel][eloc], d = p.dst[rel][eloc];
    float2 pr = g_p[e];
    int di = (c_DOFF[rel] + d) * 2;
    float a0 = pr.x * g_ss[di + 0];
    float a1 = pr.y * g_ss[di + 1];
    const float* hsrow = g_hs + c_HSOFF[rel] + (size_t)s * 128;
    float4 h0 = *reinterpret_cast<const float4*>(hsrow + c0);
    float4 h1 = *reinterpret_cast<const float4*>(hsrow + 64 + c0);
    float4 v;
    v.x = a0 * h0.x + a1 * h1.x;
    v.y = a0 * h0.y + a1 * h1.y;
    v.z = a0 * h0.z + a1 * h1.z;
    v.w = a0 * h0.w + a1 * h1.w;
    float4* acc = reinterpret_cast<float4*>(out_acc(rel) + (size_t)d * 64 + c0);
    atomicAdd(acc, v);
}

__global__ void relu_k() {
    int gid = blockIdx.x * 256 + threadIdx.x;
    if (gid >= ACC_TOT) return;
    if (gid < NPOST * 64)
        g_h_post[gid] = fmaxf(g_acc_post[gid], 0.0f);
    else if (gid < (NPOST + NUSER) * 64) {
        int i = gid - NPOST * 64;
        g_h_user[i] = fmaxf(g_acc_user[i], 0.0f);
    } else {
        int i = gid - (NPOST + NUSER) * 64;
        g_h_ent[i] = fmaxf(g_acc_ent[i], 0.0f);
    }
}

// classifier: one warp per post node
__global__ void __launch_bounds__(256) cls_k(const float* __restrict__ w1,
                                             const float* __restrict__ b1,
                                             const float* __restrict__ w2,
                                             const float* __restrict__ b2,
                                             float* __restrict__ out) {
    int gid = blockIdx.x * 256 + threadIdx.x;
    int n = gid >> 5, lane = gid & 31;
    if (n >= NPOST) return;
    const float4* x4 = reinterpret_cast<const float4*>(g_h_post + (size_t)n * 64);
    const float4* w4 = reinterpret_cast<const float4*>(w1 + (size_t)lane * 64);
    float a = 0.0f;
#pragma unroll
    for (int k = 0; k < 16; k++) {
        float4 xv = x4[k], wv = w4[k];
        a = fmaf(xv.x, wv.x, fmaf(xv.y, wv.y, fmaf(xv.z, wv.z, fmaf(xv.w, wv.w, a))));
    }
    float h = fmaxf(a + b1[lane], 0.0f) * w2[lane];
#pragma unroll
    for (int off = 16; off > 0; off >>= 1)
        h += __shfl_xor_sync(0xffffffffu, h, off);
    if (lane == 0) out[n] = h + b2[0];
}

// ---------------- launch ----------------
extern "C" void kernel_launch(void* const* d_in, const int* in_sizes, int n_in,
                              void* d_out, int out_size) {
    const float* x_post = (const float*)d_in[0];
    const float* x_user = (const float*)d_in[1];
    const float* x_ent  = (const float*)d_in[2];
    EdgeParams ep;
    for (int r = 0; r < 6; r++) {
        ep.src[r] = (const int*)d_in[3 + 2 * r];
        ep.dst[r] = (const int*)d_in[4 + 2 * r];
    }
    const float* post_w = (const float*)d_in[15];
    const float* post_b = (const float*)d_in[16];
    const float* user_w = (const float*)d_in[17];
    const float* user_b = (const float*)d_in[18];
    const float* ent_w  = (const float*)d_in[19];
    const float* ent_b  = (const float*)d_in[20];
    const float* W_src  = (const float*)d_in[21];
    const float* W_dst  = (const float*)d_in[22];
    const float* a_src  = (const float*)d_in[23];
    const float* a_dst  = (const float*)d_in[24];
    const float* gat_b  = (const float*)d_in[25];
    const float* cls_w1 = (const float*)d_in[26];
    const float* cls_b1 = (const float*)d_in[27];
    const float* cls_w2 = (const float*)d_in[28];
    const float* cls_b2 = (const float*)d_in[29];
    float* out = (float*)d_out;

    proj_post_k<<<782, 256>>>(x_post, post_w, post_b);
    proj_user_k<<<391, 256>>>(x_user, user_w, user_b);
    proj_ent_k<<<157, 256>>>(x_ent, ent_w, ent_b);
    u_k<<<12, 256>>>(W_src, W_dst, a_src, a_dst);

    for (int l = 0; l < 2; l++) {
        hs_all_k<<<3128, 256>>>(W_src, l);
        al_k<<<3204, 256>>>(l);
        reset_k<<<42500, 256>>>(gat_b, l);
        edge_max_k<<<6055, 256>>>(ep);
        edge_sum_k<<<6055, 256>>>(ep);
        inv_k<<<3282, 256>>>();
        edge_msg_k<<<96875, 256>>>(ep);
        relu_k<<<42500, 256>>>();
    }
    cls_k<<<12500, 256>>>(cls_w1, cls_b1, cls_w2, cls_b2, out);
}

// round 9
// speedup vs baseline: 1.5763x; 1.5763x over previous
#include <cuda_runtime.h>
#include <cuda_bf16.h>
#include <cstdint>

#define NPOST 100000
#define NUSER 50000
#define NENT  20000
#define NEDGE_TOT 1550000
#define NSRC_TOT 400000     // sum of per-relation src node counts
#define NDST_TOT 420000     // sum of per-relation dst node counts
#define ACC_TOT  10880000   // (NPOST+NUSER+NENT)*64

// ---------------- static device scratch ----------------
__device__ float g_h_post[NPOST * 64];
__device__ float g_h_user[NUSER * 64];
__device__ float g_h_ent [NENT  * 64];
__device__ float g_acc_post[NPOST * 64];
__device__ float g_acc_user[NUSER * 64];
__device__ float g_acc_ent [NENT  * 64];
__device__ float g_hs[51200000];        // concat per-relation hs [N_src][128]
__device__ float2 g_al_s[NSRC_TOT];
__device__ float2 g_al_d[NDST_TOT];
__device__ float        g_ss[NDST_TOT * 2]; // softmax denom -> inverted in place
__device__ float2 g_p[NEDGE_TOT];           // unnormalized softmax numerators
__device__ float g_u[3072];             // folded attention vectors [l][r][side][h][64]
__device__ unsigned int g_smax[24];     // encoded per-(layer,rel,head) max of al_s

// ---------------- constant tables ----------------
__constant__ int c_EPFX[7]  = {0, 100000, 300000, 500000, 900000, 1300000, 1550000};
__constant__ int c_SOFF[6]  = {0, 50000, 100000, 200000, 250000, 300000};
__constant__ int c_DOFF[6]  = {0, 100000, 200000, 220000, 270000, 320000};
__constant__ int c_HSOFF[6] = {0, 6400000, 12800000, 25600000, 32000000, 38400000};
__constant__ int c_ALPFX[13] = {0, 50000, 100000, 200000, 250000, 300000, 400000,
                                500000, 600000, 620000, 670000, 720000, 820000};
// hs dispatch: blocks of 64 nodes per relation: {782,782,1563,782,782,1563}
__constant__ int c_HSBLK[7] = {0, 782, 1564, 3127, 3909, 4691, 6254};
__constant__ int c_NSRC[6]  = {50000, 50000, 100000, 50000, 50000, 100000};

struct EdgeParams { const int* src[6]; const int* dst[6]; };

// ---------------- helpers ----------------
__device__ __forceinline__ const float* src_x(int rel) {
    return (rel == 2 || rel == 5) ? g_h_post : g_h_user;
}
__device__ __forceinline__ const float* dst_x(int rel) {
    if (rel == 2) return g_h_ent;
    if (rel == 3 || rel == 4) return g_h_user;
    return g_h_post;
}
__device__ __forceinline__ float* out_acc(int rel) {
    if (rel == 2) return g_acc_ent;
    if (rel == 3 || rel == 4) return g_acc_user;
    return g_acc_post;
}
__device__ __forceinline__ float lrelu(float x) { return x > 0.0f ? x : 0.2f * x; }
__device__ __forceinline__ unsigned int encf(float f) {
    unsigned int u = __float_as_uint(f);
    return (u & 0x80000000u) ? ~u : (u | 0x80000000u);
}
__device__ __forceinline__ float decf(unsigned int u) {
    return (u & 0x80000000u) ? __uint_as_float(u & 0x7fffffffu) : __uint_as_float(~u);
}
__device__ __forceinline__ int edge_rel(int gid) {
    int rel = 0;
#pragma unroll
    for (int r = 1; r < 6; r++) if (gid >= c_EPFX[r]) rel = r;
    return rel;
}

// ---------------- tiled GEMM: Y[n][m] = sum_k X[n][k]*W[m][k] (+ B[m]) ----------------
// Block = 256 threads handles 64 nodes x M cols. K, M compile-time. K % 32 == 0.
// (round-5/7 proven version; fat-tile variants regressed via bank conflicts +
//  register pressure — do not re-tile.)
template <int K, int M>
__device__ __forceinline__ void gemm_device(const float* __restrict__ X,
                                            const float* __restrict__ W,
                                            const float* __restrict__ B,
                                            float* __restrict__ Y, int N, int n0)
{
    constexpr int KT  = 32;
    constexpr int TM  = M / 16;        // cols per thread (4 or 8)
    constexpr int TPR = 256 / M;       // threads per W row
    constexpr int LW  = 32 / TPR;      // k's per thread for W staging
    __shared__ float Xs[KT * 64];
    __shared__ float Ws[KT * (M + 4)];

    const int t  = threadIdx.x;
    const int tx = t & 15, ty = t >> 4;
    const int xn = t & 63, xk0 = (t >> 6) * 8;
    const int wm = t / TPR, wk0 = (t % TPR) * LW;

    float acc[4][TM];
#pragma unroll
    for (int i = 0; i < 4; i++)
#pragma unroll
        for (int j = 0; j < TM; j++) acc[i][j] = 0.0f;

    const bool xok = (n0 + xn) < N;

    for (int k0 = 0; k0 < K; k0 += KT) {
        float4 a = make_float4(0.f, 0.f, 0.f, 0.f);
        float4 b = make_float4(0.f, 0.f, 0.f, 0.f);
        if (xok) {
            const float4* g = reinterpret_cast<const float4*>(
                X + (size_t)(n0 + xn) * K + k0 + xk0);
            a = g[0]; b = g[1];
        }
        Xs[(xk0 + 0) * 64 + xn] = a.x; Xs[(xk0 + 1) * 64 + xn] = a.y;
        Xs[(xk0 + 2) * 64 + xn] = a.z; Xs[(xk0 + 3) * 64 + xn] = a.w;
        Xs[(xk0 + 4) * 64 + xn] = b.x; Xs[(xk0 + 5) * 64 + xn] = b.y;
        Xs[(xk0 + 6) * 64 + xn] = b.z; Xs[(xk0 + 7) * 64 + xn] = b.w;

#pragma unroll
        for (int j = 0; j < LW; j += 4) {
            float4 w4 = *reinterpret_cast<const float4*>(
                W + (size_t)wm * K + k0 + wk0 + j);
            Ws[(wk0 + j + 0) * (M + 4) + wm] = w4.x;
            Ws[(wk0 + j + 1) * (M + 4) + wm] = w4.y;
            Ws[(wk0 + j + 2) * (M + 4) + wm] = w4.z;
            Ws[(wk0 + j + 3) * (M + 4) + wm] = w4.w;
        }
        __syncthreads();

#pragma unroll
        for (int kk = 0; kk < KT; kk++) {
            float4 xv4 = *reinterpret_cast<const float4*>(&Xs[kk * 64 + ty * 4]);
            float xv[4] = {xv4.x, xv4.y, xv4.z, xv4.w};
            float wv[TM];
#pragma unroll
            for (int j = 0; j < TM; j += 4) {
                float4 w4 = *reinterpret_cast<const float4*>(
                    &Ws[kk * (M + 4) + tx * TM + j]);
                wv[j] = w4.x; wv[j + 1] = w4.y; wv[j + 2] = w4.z; wv[j + 3] = w4.w;
            }
#pragma unroll
            for (int i = 0; i < 4; i++)
#pragma unroll
                for (int j = 0; j < TM; j++)
                    acc[i][j] = fmaf(xv[i], wv[j], acc[i][j]);
        }
        __syncthreads();
    }

    float bj[TM];
#pragma unroll
    for (int j = 0; j < TM; j++) bj[j] = B ? B[tx * TM + j] : 0.0f;
#pragma unroll
    for (int i = 0; i < 4; i++) {
        int n = n0 + ty * 4 + i;
        if (n < N) {
#pragma unroll
            for (int j = 0; j < TM; j += 4) {
                float4 v;
                v.x = acc[i][j + 0] + bj[j + 0];
                v.y = acc[i][j + 1] + bj[j + 1];
                v.z = acc[i][j + 2] + bj[j + 2];
                v.w = acc[i][j + 3] + bj[j + 3];
                *reinterpret_cast<float4*>(Y + (size_t)n * M + tx * TM + j) = v;
            }
        }
    }
}

// ---------------- kernels ----------------
__global__ void __launch_bounds__(256) proj_post_k(const float* X, const float* W, const float* B) {
    gemm_device<768, 64>(X, W, B, g_h_post, NPOST, blockIdx.x * 64);
}
__global__ void __launch_bounds__(256) proj_user_k(const float* X, const float* W, const float* B) {
    gemm_device<32, 64>(X, W, B, g_h_user, NUSER, blockIdx.x * 64);
}
__global__ void __launch_bounds__(256) proj_ent_k(const float* X, const float* W, const float* B) {
    gemm_device<64, 64>(X, W, B, g_h_ent, NENT, blockIdx.x * 64);
}
// hs for all 6 relations in one launch: hs = x_src @ W_src[l,rel].T : [N_src, 128]
__global__ void __launch_bounds__(256) hs_all_k(const float* __restrict__ Wsrc, int l) {
    int b = blockIdx.x;
    int rel = 0;
#pragma unroll
    for (int r = 1; r < 6; r++) if (b >= c_HSBLK[r]) rel = r;
    gemm_device<64, 128>(src_x(rel), Wsrc + ((size_t)l * 6 + rel) * 8192, nullptr,
                         g_hs + c_HSOFF[rel], c_NSRC[rel], (b - c_HSBLK[rel]) * 64);
}

// folded attention vectors: u[l][r][side][h][k] = sum_c a[l][r][h][c] * W[l][r][h*64+c][k]
// also zeroes g_smax for both layers (runs once per launch, before all al_k).
__global__ void u_k(const float* __restrict__ Ws, const float* __restrict__ Wd,
                    const float* __restrict__ as_, const float* __restrict__ ad_) {
    int id = blockIdx.x * 256 + threadIdx.x;
    if (blockIdx.x == 0 && threadIdx.x < 24) g_smax[threadIdx.x] = 0u;
    if (id >= 3072) return;
    int k = id & 63, h = (id >> 6) & 1, side = (id >> 7) & 1, rl = id >> 8;
    const float* a = (side ? ad_ : as_) + (size_t)rl * 128 + h * 64;
    const float* W = (side ? Wd : Ws) + (size_t)rl * 8192 + (size_t)h * 64 * 64;
    float u = 0.0f;
#pragma unroll 8
    for (int c = 0; c < 64; c++) u = fmaf(a[c], W[c * 64 + k], u);
    g_u[id] = u;
}

// attention scalars per node for all 12 (relation,side) tasks.
// side=0 additionally reduces the per-(rel,head) max of al_s into g_smax.
__global__ void __launch_bounds__(256) al_k(int l) {
    __shared__ unsigned int s_max[12];
    if (threadIdx.x < 12) s_max[threadIdx.x] = 0u;
    __syncthreads();

    int gid = blockIdx.x * 256 + threadIdx.x;
    if (gid < 820000) {
        int t = 0;
#pragma unroll
        for (int i = 1; i < 12; i++) if (gid >= c_ALPFX[i]) t = i;
        int n = gid - c_ALPFX[t];
        int side = (t >= 6) ? 1 : 0;
        int rel = side ? t - 6 : t;
        const float* xr = (side ? dst_x(rel) : src_x(rel)) + (size_t)n * 64;
        const float4* x4 = reinterpret_cast<const float4*>(xr);
        const float4* u4 = reinterpret_cast<const float4*>(
            g_u + ((size_t)(l * 6 + rel) * 2 + side) * 128);
        float a0 = 0.0f, a1 = 0.0f;
#pragma unroll
        for (int k = 0; k < 16; k++) {
            float4 xv = x4[k], u0 = u4[k], u1 = u4[16 + k];
            a0 = fmaf(xv.x, u0.x, fmaf(xv.y, u0.y, fmaf(xv.z, u0.z, fmaf(xv.w, u0.w, a0))));
            a1 = fmaf(xv.x, u1.x, fmaf(xv.y, u1.y, fmaf(xv.z, u1.z, fmaf(xv.w, u1.w, a1))));
        }
        float2 r; r.x = a0; r.y = a1;
        if (side) {
            g_al_d[c_DOFF[rel] + n] = r;
        } else {
            g_al_s[c_SOFF[rel] + n] = r;
            atomicMax(&s_max[rel * 2 + 0], encf(a0));
            atomicMax(&s_max[rel * 2 + 1], encf(a1));
        }
    }
    __syncthreads();
    if (threadIdx.x < 12 && s_max[threadIdx.x] != 0u)
        atomicMax(&g_smax[l * 12 + threadIdx.x], s_max[threadIdx.x]);
}

// fused: zero softmax denominators + init accumulators with summed gat biases
__global__ void reset_k(const float* __restrict__ gb, int l) {
    int gid = blockIdx.x * 256 + threadIdx.x;
    if (gid >= ACC_TOT) return;
    if (gid < NDST_TOT * 2) g_ss[gid] = 0.0f;
    int c = gid & 63;
    const float* b = gb + l * 384;  // [6][64]
    if (gid < NPOST * 64)
        g_acc_post[gid] = b[0 * 64 + c] + b[1 * 64 + c] + b[5 * 64 + c];
    else if (gid < (NPOST + NUSER) * 64)
        g_acc_user[gid - NPOST * 64] = b[3 * 64 + c] + b[4 * 64 + c];
    else
        g_acc_ent[gid - (NPOST + NUSER) * 64] = b[2 * 64 + c];
}

// stable-softmax numerators using the per-relation src-max upper bound:
// m'[d,h] = lrelu(smax[rel,h] + al_d[d,h]) >= max_e lrelu(al_s+al_d)  (lrelu monotonic)
__global__ void __launch_bounds__(256) edge_sum_k(EdgeParams p, int l) {
    int gid = blockIdx.x * 256 + threadIdx.x;
    if (gid >= NEDGE_TOT) return;
    int rel = edge_rel(gid);
    int e = gid - c_EPFX[rel];
    int s = p.src[rel][e], d = p.dst[rel][e];
    float2 as = g_al_s[c_SOFF[rel] + s];
    float2 ad = g_al_d[c_DOFF[rel] + d];
    float sm0 = decf(g_smax[l * 12 + rel * 2 + 0]);
    float sm1 = decf(g_smax[l * 12 + rel * 2 + 1]);
    float e0 = lrelu(as.x + ad.x);
    float e1 = lrelu(as.y + ad.y);
    float m0 = lrelu(sm0 + ad.x);
    float m1 = lrelu(sm1 + ad.y);
    int di = (c_DOFF[rel] + d) * 2;
    float p0 = __expf(e0 - m0);
    float p1 = __expf(e1 - m1);
    atomicAdd(&g_ss[di + 0], p0);
    atomicAdd(&g_ss[di + 1], p1);
    float2 pr; pr.x = p0; pr.y = p1;
    g_p[gid] = pr;
}

// invert denominators in place, folding in head-mean 0.5x
__global__ void inv_k() {
    int gid = blockIdx.x * 256 + threadIdx.x;
    if (gid >= NDST_TOT * 2) return;
    g_ss[gid] = 0.5f / (g_ss[gid] + 1e-16f);
}

// 16 threads per edge, 4 channels each; single float4 vector atomic per thread
__global__ void __launch_bounds__(256) edge_msg_k(EdgeParams p) {
    int gid = blockIdx.x * 256 + threadIdx.x;
    if (gid >= NEDGE_TOT * 16) return;
    int e = gid >> 4, c0 = (gid & 15) << 2;
    int rel = edge_rel(e);
    int eloc = e - c_EPFX[rel];
    int s = p.src[rel][eloc], d = p.dst[rel][eloc];
    float2 pr = g_p[e];
    int di = (c_DOFF[rel] + d) * 2;
    float a0 = pr.x * g_ss[di + 0];
    float a1 = pr.y * g_ss[di + 1];
    const float* hsrow = g_hs + c_HSOFF[rel] + (size_t)s * 128;
    float4 h0 = *reinterpret_cast<const float4*>(hsrow + c0);
    float4 h1 = *reinterpret_cast<const float4*>(hsrow + 64 + c0);
    float4 v;
    v.x = a0 * h0.x + a1 * h1.x;
    v.y = a0 * h0.y + a1 * h1.y;
    v.z = a0 * h0.z + a1 * h1.z;
    v.w = a0 * h0.w + a1 * h1.w;
    float4* acc = reinterpret_cast<float4*>(out_acc(rel) + (size_t)d * 64 + c0);
    atomicAdd(acc, v);
}

__global__ void relu_k() {
    int gid = blockIdx.x * 256 + threadIdx.x;
    if (gid >= ACC_TOT) return;
    if (gid < NPOST * 64)
        g_h_post[gid] = fmaxf(g_acc_post[gid], 0.0f);
    else if (gid < (NPOST + NUSER) * 64) {
        int i = gid - NPOST * 64;
        g_h_user[i] = fmaxf(g_acc_user[i], 0.0f);
    } else {
        int i = gid - (NPOST + NUSER) * 64;
        g_h_ent[i] = fmaxf(g_acc_ent[i], 0.0f);
    }
}

// classifier: one warp per post node
__global__ void __launch_bounds__(256) cls_k(const float* __restrict__ w1,
                                             const float* __restrict__ b1,
                                             const float* __restrict__ w2,
                                             const float* __restrict__ b2,
                                             float* __restrict__ out) {
    int gid = blockIdx.x * 256 + threadIdx.x;
    int n = gid >> 5, lane = gid & 31;
    if (n >= NPOST) return;
    const float4* x4 = reinterpret_cast<const float4*>(g_h_post + (size_t)n * 64);
    const float4* w4 = reinterpret_cast<const float4*>(w1 + (size_t)lane * 64);
    float a = 0.0f;
#pragma unroll
    for (int k = 0; k < 16; k++) {
        float4 xv = x4[k], wv = w4[k];
        a = fmaf(xv.x, wv.x, fmaf(xv.y, wv.y, fmaf(xv.z, wv.z, fmaf(xv.w, wv.w, a))));
    }
    float h = fmaxf(a + b1[lane], 0.0f) * w2[lane];
#pragma unroll
    for (int off = 16; off > 0; off >>= 1)
        h += __shfl_xor_sync(0xffffffffu, h, off);
    if (lane == 0) out[n] = h + b2[0];
}

// ---------------- launch ----------------
extern "C" void kernel_launch(void* const* d_in, const int* in_sizes, int n_in,
                              void* d_out, int out_size) {
    const float* x_post = (const float*)d_in[0];
    const float* x_user = (const float*)d_in[1];
    const float* x_ent  = (const float*)d_in[2];
    EdgeParams ep;
    for (int r = 0; r < 6; r++) {
        ep.src[r] = (const int*)d_in[3 + 2 * r];
        ep.dst[r] = (const int*)d_in[4 + 2 * r];
    }
    const float* post_w = (const float*)d_in[15];
    const float* post_b = (const float*)d_in[16];
    const float* user_w = (const float*)d_in[17];
    const float* user_b = (const float*)d_in[18];
    const float* ent_w  = (const float*)d_in[19];
    const float* ent_b  = (const float*)d_in[20];
    const float* W_src  = (const float*)d_in[21];
    const float* W_dst  = (const float*)d_in[22];
    const float* a_src  = (const float*)d_in[23];
    const float* a_dst  = (const float*)d_in[24];
    const float* gat_b  = (const float*)d_in[25];
    const float* cls_w1 = (const float*)d_in[26];
    const float* cls_b1 = (const float*)d_in[27];
    const float* cls_w2 = (const float*)d_in[28];
    const float* cls_b2 = (const float*)d_in[29];
    float* out = (float*)d_out;

    proj_post_k<<<1563, 256>>>(x_post, post_w, post_b);
    proj_user_k<<<782, 256>>>(x_user, user_w, user_b);
    proj_ent_k<<<313, 256>>>(x_ent, ent_w, ent_b);
    u_k<<<12, 256>>>(W_src, W_dst, a_src, a_dst);

    for (int l = 0; l < 2; l++) {
        hs_all_k<<<6254, 256>>>(W_src, l);
        al_k<<<3204, 256>>>(l);
        reset_k<<<42500, 256>>>(gat_b, l);
        edge_sum_k<<<6055, 256>>>(ep, l);
        inv_k<<<3282, 256>>>();
        edge_msg_k<<<96875, 256>>>(ep);
        relu_k<<<42500, 256>>>();
    }
    cls_k<<<12500, 256>>>(cls_w1, cls_b1, cls_w2, cls_b2, out);
}

// round 10
// speedup vs baseline: 2.1725x; 1.3782x over previous
#include <cuda_runtime.h>
#include <cuda_bf16.h>
#include <cstdint>

#define NPOST 100000
#define NUSER 50000
#define NENT  20000
#define NSRC_TOT 400000
#define NDST_TOT 420000
#define BIG (1 << 29)

// ---------------- static device scratch ----------------
__device__ float g_h_post[NPOST * 64];
__device__ float g_h_user[NUSER * 64];
__device__ float g_acc_post[NPOST * 64];
__device__ float g_acc_user[NUSER * 64];
__device__ float g_hs[51200000];        // concat per-relation hs [N_src][128]
__device__ float2 g_al_s[NSRC_TOT];
__device__ float2 g_al_d[NDST_TOT];
__device__ float        g_ss[NDST_TOT * 2]; // softmax denom -> inverted in place
__device__ float2 g_p[1350000];             // unnormalized softmax numerators (layer-local)
__device__ float g_u[3072];             // folded attention vectors [l][r][side][h][64]
__device__ unsigned int g_smax[24];     // encoded per-(layer,rel,head) max of al_s

// ---------------- constant tables ----------------
// per-relation tables (indexed by TRUE relation id 0..5)
__constant__ int c_SOFF[6]  = {0, 50000, 100000, 200000, 250000, 300000};
__constant__ int c_DOFF[6]  = {0, 100000, 200000, 220000, 270000, 320000};
__constant__ int c_HSOFF[6] = {0, 6400000, 12800000, 25600000, 32000000, 38400000};
__constant__ int c_NSRC[6]  = {50000, 50000, 100000, 50000, 50000, 100000};

// per-layer live-relation dispatch (ent + rel2 dead; layer1 keeps only post rels)
// hs blocks of 64 nodes: L0 rels {0,1,3,4,5} -> {782,782,782,782,1563}
//                        L1 rels {0,1,5}     -> {782,782,1563}
__constant__ int c_HSBLK2[2][5] = {{0, 782, 1564, 2346, 3128},
                                   {0, 782, 1564, BIG, BIG}};
__constant__ int c_HSREL2[2][5] = {{0, 1, 3, 4, 5}, {0, 1, 5, 5, 5}};
// al tasks: (rel, side); L0: 10 tasks / 700000; L1: 6 tasks / 500000
__constant__ int c_ALPFX2[2][10] = {
    {0, 50000, 100000, 150000, 200000, 300000, 400000, 500000, 550000, 600000},
    {0, 50000, 100000, 200000, 300000, 400000, BIG, BIG, BIG, BIG}};
__constant__ int c_ALREL2[2][10] = {{0, 1, 3, 4, 5, 0, 1, 3, 4, 5},
                                    {0, 1, 5, 0, 1, 5, 5, 5, 5, 5}};
__constant__ int c_ALSIDE2[2][10] = {{0, 0, 0, 0, 0, 1, 1, 1, 1, 1},
                                     {0, 0, 0, 1, 1, 1, 1, 1, 1, 1}};
__constant__ int c_ALN[2] = {700000, 500000};
// edges: L0 rels {0,1,3,4,5} sizes {100k,200k,400k,400k,250k}; L1 {0,1,5}
__constant__ int c_EPFX2[2][5] = {{0, 100000, 300000, 700000, 1100000},
                                  {0, 100000, 300000, BIG, BIG}};
__constant__ int c_EREL2[2][5] = {{0, 1, 3, 4, 5}, {0, 1, 5, 5, 5}};
__constant__ int c_EN[2] = {1350000, 550000};
__constant__ int c_ACCN[2] = {9600000, 6400000};  // post+user / post only

struct EdgeParams { const int* src[6]; const int* dst[6]; };

// ---------------- helpers ----------------
__device__ __forceinline__ const float* src_x(int rel) {
    return (rel == 5) ? g_h_post : g_h_user;   // live rels: 0,1,3,4 user; 5 post
}
__device__ __forceinline__ const float* dst_x(int rel) {
    return (rel == 3 || rel == 4) ? g_h_user : g_h_post;
}
__device__ __forceinline__ float* out_acc(int rel) {
    return (rel == 3 || rel == 4) ? g_acc_user : g_acc_post;
}
__device__ __forceinline__ float lrelu(float x) { return x > 0.0f ? x : 0.2f * x; }
__device__ __forceinline__ unsigned int encf(float f) {
    unsigned int u = __float_as_uint(f);
    return (u & 0x80000000u) ? ~u : (u | 0x80000000u);
}
__device__ __forceinline__ float decf(unsigned int u) {
    return (u & 0x80000000u) ? __uint_as_float(u & 0x7fffffffu) : __uint_as_float(~u);
}

// ---------------- tiled GEMM: Y[n][m] = sum_k X[n][k]*W[m][k] (+ B[m]) ----------------
// Block = 256 threads handles 64 nodes x M cols (proven round-5 tile; do not re-tile).
template <int K, int M>
__device__ __forceinline__ void gemm_device(const float* __restrict__ X,
                                            const float* __restrict__ W,
                                            const float* __restrict__ B,
                                            float* __restrict__ Y, int N, int n0)
{
    constexpr int KT  = 32;
    constexpr int TM  = M / 16;
    constexpr int TPR = 256 / M;
    constexpr int LW  = 32 / TPR;
    __shared__ float Xs[KT * 64];
    __shared__ float Ws[KT * (M + 4)];

    const int t  = threadIdx.x;
    const int tx = t & 15, ty = t >> 4;
    const int xn = t & 63, xk0 = (t >> 6) * 8;
    const int wm = t / TPR, wk0 = (t % TPR) * LW;

    float acc[4][TM];
#pragma unroll
    for (int i = 0; i < 4; i++)
#pragma unroll
        for (int j = 0; j < TM; j++) acc[i][j] = 0.0f;

    const bool xok = (n0 + xn) < N;

    for (int k0 = 0; k0 < K; k0 += KT) {
        float4 a = make_float4(0.f, 0.f, 0.f, 0.f);
        float4 b = make_float4(0.f, 0.f, 0.f, 0.f);
        if (xok) {
            const float4* g = reinterpret_cast<const float4*>(
                X + (size_t)(n0 + xn) * K + k0 + xk0);
            a = g[0]; b = g[1];
        }
        Xs[(xk0 + 0) * 64 + xn] = a.x; Xs[(xk0 + 1) * 64 + xn] = a.y;
        Xs[(xk0 + 2) * 64 + xn] = a.z; Xs[(xk0 + 3) * 64 + xn] = a.w;
        Xs[(xk0 + 4) * 64 + xn] = b.x; Xs[(xk0 + 5) * 64 + xn] = b.y;
        Xs[(xk0 + 6) * 64 + xn] = b.z; Xs[(xk0 + 7) * 64 + xn] = b.w;

#pragma unroll
        for (int j = 0; j < LW; j += 4) {
            float4 w4 = *reinterpret_cast<const float4*>(
                W + (size_t)wm * K + k0 + wk0 + j);
            Ws[(wk0 + j + 0) * (M + 4) + wm] = w4.x;
            Ws[(wk0 + j + 1) * (M + 4) + wm] = w4.y;
            Ws[(wk0 + j + 2) * (M + 4) + wm] = w4.z;
            Ws[(wk0 + j + 3) * (M + 4) + wm] = w4.w;
        }
        __syncthreads();

#pragma unroll
        for (int kk = 0; kk < KT; kk++) {
            float4 xv4 = *reinterpret_cast<const float4*>(&Xs[kk * 64 + ty * 4]);
            float xv[4] = {xv4.x, xv4.y, xv4.z, xv4.w};
            float wv[TM];
#pragma unroll
            for (int j = 0; j < TM; j += 4) {
                float4 w4 = *reinterpret_cast<const float4*>(
                    &Ws[kk * (M + 4) + tx * TM + j]);
                wv[j] = w4.x; wv[j + 1] = w4.y; wv[j + 2] = w4.z; wv[j + 3] = w4.w;
            }
#pragma unroll
            for (int i = 0; i < 4; i++)
#pragma unroll
                for (int j = 0; j < TM; j++)
                    acc[i][j] = fmaf(xv[i], wv[j], acc[i][j]);
        }
        __syncthreads();
    }

    float bj[TM];
#pragma unroll
    for (int j = 0; j < TM; j++) bj[j] = B ? B[tx * TM + j] : 0.0f;
#pragma unroll
    for (int i = 0; i < 4; i++) {
        int n = n0 + ty * 4 + i;
        if (n < N) {
#pragma unroll
            for (int j = 0; j < TM; j += 4) {
                float4 v;
                v.x = acc[i][j + 0] + bj[j + 0];
                v.y = acc[i][j + 1] + bj[j + 1];
                v.z = acc[i][j + 2] + bj[j + 2];
                v.w = acc[i][j + 3] + bj[j + 3];
                *reinterpret_cast<float4*>(Y + (size_t)n * M + tx * TM + j) = v;
            }
        }
    }
}

// ---------------- standalone projection kernels ----------------
__global__ void __launch_bounds__(256) proj_post_k(const float* X, const float* W, const float* B) {
    gemm_device<768, 64>(X, W, B, g_h_post, NPOST, blockIdx.x * 64);
}
__global__ void __launch_bounds__(256) proj_user_k(const float* X, const float* W, const float* B) {
    gemm_device<32, 64>(X, W, B, g_h_user, NUSER, blockIdx.x * 64);
}

// folded attention vectors: u[l][r][side][h][k] = sum_c a[l][r][h][c] * W[l][r][h*64+c][k]
// also zeroes g_smax for both layers.
__global__ void u_k(const float* __restrict__ Ws, const float* __restrict__ Wd,
                    const float* __restrict__ as_, const float* __restrict__ ad_) {
    int id = blockIdx.x * 256 + threadIdx.x;
    if (blockIdx.x == 0 && threadIdx.x < 24) g_smax[threadIdx.x] = 0u;
    if (id >= 3072) return;
    int k = id & 63, h = (id >> 6) & 1, side = (id >> 7) & 1, rl = id >> 8;
    const float* a = (side ? ad_ : as_) + (size_t)rl * 128 + h * 64;
    const float* W = (side ? Wd : Ws) + (size_t)rl * 8192 + (size_t)h * 64 * 64;
    float u = 0.0f;
#pragma unroll 8
    for (int c = 0; c < 64; c++) u = fmaf(a[c], W[c * 64 + k], u);
    g_u[id] = u;
}

// ---------------- fused stage A: hs GEMMs | al scalars | reset ----------------
// All three depend only on the previous layer's features; co-scheduled in one grid.
__global__ void __launch_bounds__(256) stage_a_k(const float* __restrict__ Wsrc,
                                                 const float* __restrict__ gb,
                                                 int l, int nhs, int nalb) {
    int b = blockIdx.x;
    if (b < nhs) {
        // --- hs segment: hs = x_src @ W_src[l,rel].T : [N_src, 128] ---
        int idx = 0;
#pragma unroll
        for (int r = 1; r < 5; r++) if (b >= c_HSBLK2[l][r]) idx = r;
        int rel = c_HSREL2[l][idx];
        gemm_device<64, 128>(src_x(rel), Wsrc + ((size_t)l * 6 + rel) * 8192, nullptr,
                             g_hs + c_HSOFF[rel], c_NSRC[rel],
                             (b - c_HSBLK2[l][idx]) * 64);
        return;
    }
    if (b < nhs + nalb) {
        // --- al segment: attention scalars; side=0 reduces per-(rel,head) src max ---
        __shared__ unsigned int s_max[12];
        if (threadIdx.x < 12) s_max[threadIdx.x] = 0u;
        __syncthreads();
        int gid = (b - nhs) * 256 + threadIdx.x;
        if (gid < c_ALN[l]) {
            int t = 0;
#pragma unroll
            for (int i = 1; i < 10; i++) if (gid >= c_ALPFX2[l][i]) t = i;
            int n = gid - c_ALPFX2[l][t];
            int rel = c_ALREL2[l][t];
            int side = c_ALSIDE2[l][t];
            const float* xr = (side ? dst_x(rel) : src_x(rel)) + (size_t)n * 64;
            const float4* x4 = reinterpret_cast<const float4*>(xr);
            const float4* u4 = reinterpret_cast<const float4*>(
                g_u + ((size_t)(l * 6 + rel) * 2 + side) * 128);
            float a0 = 0.0f, a1 = 0.0f;
#pragma unroll
            for (int k = 0; k < 16; k++) {
                float4 xv = x4[k], u0 = u4[k], u1 = u4[16 + k];
                a0 = fmaf(xv.x, u0.x, fmaf(xv.y, u0.y, fmaf(xv.z, u0.z, fmaf(xv.w, u0.w, a0))));
                a1 = fmaf(xv.x, u1.x, fmaf(xv.y, u1.y, fmaf(xv.z, u1.z, fmaf(xv.w, u1.w, a1))));
            }
            float2 r; r.x = a0; r.y = a1;
            if (side) {
                g_al_d[c_DOFF[rel] + n] = r;
            } else {
                g_al_s[c_SOFF[rel] + n] = r;
                atomicMax(&s_max[rel * 2 + 0], encf(a0));
                atomicMax(&s_max[rel * 2 + 1], encf(a1));
            }
        }
        __syncthreads();
        if (threadIdx.x < 12 && s_max[threadIdx.x] != 0u)
            atomicMax(&g_smax[l * 12 + threadIdx.x], s_max[threadIdx.x]);
        return;
    }
    // --- reset segment: zero ss + init accumulators with summed gat biases ---
    int gid = (b - nhs - nalb) * 256 + threadIdx.x;
    if (gid >= c_ACCN[l]) return;
    if (gid < NDST_TOT * 2) g_ss[gid] = 0.0f;
    int c = gid & 63;
    const float* bb = gb + l * 384;  // [6][64]
    if (gid < NPOST * 64)
        g_acc_post[gid] = bb[0 * 64 + c] + bb[1 * 64 + c] + bb[5 * 64 + c];
    else
        g_acc_user[gid - NPOST * 64] = bb[3 * 64 + c] + bb[4 * 64 + c];
}

// stable-softmax numerators using the per-relation src-max upper bound
__global__ void __launch_bounds__(256) edge_sum_k(EdgeParams p, int l) {
    int gid = blockIdx.x * 256 + threadIdx.x;
    if (gid >= c_EN[l]) return;
    int idx = 0;
#pragma unroll
    for (int r = 1; r < 5; r++) if (gid >= c_EPFX2[l][r]) idx = r;
    int rel = c_EREL2[l][idx];
    int e = gid - c_EPFX2[l][idx];
    int s = p.src[rel][e], d = p.dst[rel][e];
    float2 as = g_al_s[c_SOFF[rel] + s];
    float2 ad = g_al_d[c_DOFF[rel] + d];
    float sm0 = decf(g_smax[l * 12 + rel * 2 + 0]);
    float sm1 = decf(g_smax[l * 12 + rel * 2 + 1]);
    float e0 = lrelu(as.x + ad.x);
    float e1 = lrelu(as.y + ad.y);
    float m0 = lrelu(sm0 + ad.x);
    float m1 = lrelu(sm1 + ad.y);
    int di = (c_DOFF[rel] + d) * 2;
    float p0 = __expf(e0 - m0);
    float p1 = __expf(e1 - m1);
    atomicAdd(&g_ss[di + 0], p0);
    atomicAdd(&g_ss[di + 1], p1);
    float2 pr; pr.x = p0; pr.y = p1;
    g_p[gid] = pr;
}

// invert denominators in place, folding in head-mean 0.5x
__global__ void inv_k() {
    int gid = blockIdx.x * 256 + threadIdx.x;
    if (gid >= NDST_TOT * 2) return;
    g_ss[gid] = 0.5f / (g_ss[gid] + 1e-16f);
}

// 16 threads per edge, 4 channels each; single float4 vector atomic per thread
__global__ void __launch_bounds__(256) edge_msg_k(EdgeParams p, int l) {
    int gid = blockIdx.x * 256 + threadIdx.x;
    int e = gid >> 4, c0 = (gid & 15) << 2;
    if (e >= c_EN[l]) return;
    int idx = 0;
#pragma unroll
    for (int r = 1; r < 5; r++) if (e >= c_EPFX2[l][r]) idx = r;
    int rel = c_EREL2[l][idx];
    int eloc = e - c_EPFX2[l][idx];
    int s = p.src[rel][eloc], d = p.dst[rel][eloc];
    float2 pr = g_p[e];
    int di = (c_DOFF[rel] + d) * 2;
    float a0 = pr.x * g_ss[di + 0];
    float a1 = pr.y * g_ss[di + 1];
    const float* hsrow = g_hs + c_HSOFF[rel] + (size_t)s * 128;
    float4 h0 = *reinterpret_cast<const float4*>(hsrow + c0);
    float4 h1 = *reinterpret_cast<const float4*>(hsrow + 64 + c0);
    float4 v;
    v.x = a0 * h0.x + a1 * h1.x;
    v.y = a0 * h0.y + a1 * h1.y;
    v.z = a0 * h0.z + a1 * h1.z;
    v.w = a0 * h0.w + a1 * h1.w;
    float4* acc = reinterpret_cast<float4*>(out_acc(rel) + (size_t)d * 64 + c0);
    atomicAdd(acc, v);
}

// layer-0 relu: post + user only (ent dead)
__global__ void relu_k() {
    int gid = blockIdx.x * 256 + threadIdx.x;
    if (gid >= 9600000) return;
    if (gid < NPOST * 64)
        g_h_post[gid] = fmaxf(g_acc_post[gid], 0.0f);
    else {
        int i = gid - NPOST * 64;
        g_h_user[i] = fmaxf(g_acc_user[i], 0.0f);
    }
}

// classifier: one warp per post node; layer-2 relu folded into the load
__global__ void __launch_bounds__(256) cls_k(const float* __restrict__ w1,
                                             const float* __restrict__ b1,
                                             const float* __restrict__ w2,
                                             const float* __restrict__ b2,
                                             float* __restrict__ out) {
    int gid = blockIdx.x * 256 + threadIdx.x;
    int n = gid >> 5, lane = gid & 31;
    if (n >= NPOST) return;
    const float4* x4 = reinterpret_cast<const float4*>(g_acc_post + (size_t)n * 64);
    const float4* w4 = reinterpret_cast<const float4*>(w1 + (size_t)lane * 64);
    float a = 0.0f;
#pragma unroll
    for (int k = 0; k < 16; k++) {
        float4 xv = x4[k], wv = w4[k];
        xv.x = fmaxf(xv.x, 0.0f); xv.y = fmaxf(xv.y, 0.0f);
        xv.z = fmaxf(xv.z, 0.0f); xv.w = fmaxf(xv.w, 0.0f);
        a = fmaf(xv.x, wv.x, fmaf(xv.y, wv.y, fmaf(xv.z, wv.z, fmaf(xv.w, wv.w, a))));
    }
    float h = fmaxf(a + b1[lane], 0.0f) * w2[lane];
#pragma unroll
    for (int off = 16; off > 0; off >>= 1)
        h += __shfl_xor_sync(0xffffffffu, h, off);
    if (lane == 0) out[n] = h + b2[0];
}

// ---------------- launch ----------------
extern "C" void kernel_launch(void* const* d_in, const int* in_sizes, int n_in,
                              void* d_out, int out_size) {
    const float* x_post = (const float*)d_in[0];
    const float* x_user = (const float*)d_in[1];
    EdgeParams ep;
    for (int r = 0; r < 6; r++) {
        ep.src[r] = (const int*)d_in[3 + 2 * r];
        ep.dst[r] = (const int*)d_in[4 + 2 * r];
    }
    const float* post_w = (const float*)d_in[15];
    const float* post_b = (const float*)d_in[16];
    const float* user_w = (const float*)d_in[17];
    const float* user_b = (const float*)d_in[18];
    const float* W_src  = (const float*)d_in[21];
    const float* W_dst  = (const float*)d_in[22];
    const float* a_src  = (const float*)d_in[23];
    const float* a_dst  = (const float*)d_in[24];
    const float* gat_b  = (const float*)d_in[25];
    const float* cls_w1 = (const float*)d_in[26];
    const float* cls_b1 = (const float*)d_in[27];
    const float* cls_w2 = (const float*)d_in[28];
    const float* cls_b2 = (const float*)d_in[29];
    float* out = (float*)d_out;

    proj_post_k<<<1563, 256>>>(x_post, post_w, post_b);
    proj_user_k<<<782, 256>>>(x_user, user_w, user_b);
    u_k<<<12, 256>>>(W_src, W_dst, a_src, a_dst);

    // layer 0: rels {0,1,3,4,5}
    stage_a_k<<<4691 + 2735 + 37500, 256>>>(W_src, gat_b, 0, 4691, 2735);
    edge_sum_k<<<5274, 256>>>(ep, 0);
    inv_k<<<3282, 256>>>();
    edge_msg_k<<<84375, 256>>>(ep, 0);
    relu_k<<<37500, 256>>>();

    // layer 1: rels {0,1,5} (user/ent outputs are dead)
    stage_a_k<<<3127 + 1954 + 25000, 256>>>(W_src, gat_b, 1, 3127, 1954);
    edge_sum_k<<<2149, 256>>>(ep, 1);
    inv_k<<<3282, 256>>>();
    edge_msg_k<<<34375, 256>>>(ep, 1);

    cls_k<<<12500, 256>>>(cls_w1, cls_b1, cls_w2, cls_b2, out);
}

// round 12
// speedup vs baseline: 2.3730x; 1.0923x over previous
#include <cuda_runtime.h>
#include <cuda_bf16.h>
#include <cstdint>

#define NPOST 100000
#define NUSER 50000
#define NSRC_TOT 400000
#define NDST_TOT 420000
#define BIG (1 << 29)

// ---------------- static device scratch ----------------
__device__ float g_h_post[NPOST * 64];
__device__ float g_h_user[NUSER * 64];
__device__ float g_acc_post[NPOST * 64];
__device__ float g_acc_user[NUSER * 64];
__device__ float g_hs[51200000];        // concat per-relation hs [N_src][128]
__device__ float2 g_al_s[NSRC_TOT];
__device__ float2 g_al_d[NDST_TOT];
__device__ float        g_ss[NDST_TOT * 2]; // softmax denom -> inverted in place
__device__ float2 g_p[1350000];             // unnormalized softmax numerators
__device__ float g_u[3072];             // folded attention vectors [l][r][side][h][64]
__device__ unsigned int g_smax[24];     // encoded per-(layer,rel,head) max of al_s

// ---------------- constant tables ----------------
__constant__ int c_SOFF[6]  = {0, 50000, 100000, 200000, 250000, 300000};
__constant__ int c_DOFF[6]  = {0, 100000, 200000, 220000, 270000, 320000};
__constant__ int c_HSOFF[6] = {0, 6400000, 12800000, 25600000, 32000000, 38400000};
__constant__ int c_NSRC[6]  = {50000, 50000, 100000, 50000, 50000, 100000};

// per-layer live-relation dispatch (ent + rel2 dead; layer1 post rels only)
__constant__ int c_HSBLK2[2][5] = {{0, 782, 1564, 2346, 3128},
                                   {0, 782, 1564, BIG, BIG}};
__constant__ int c_HSREL2[2][5] = {{0, 1, 3, 4, 5}, {0, 1, 5, 5, 5}};
__constant__ int c_ALPFX2[2][10] = {
    {0, 50000, 100000, 150000, 200000, 300000, 400000, 500000, 550000, 600000},
    {0, 50000, 100000, 200000, 300000, 400000, BIG, BIG, BIG, BIG}};
__constant__ int c_ALREL2[2][10] = {{0, 1, 3, 4, 5, 0, 1, 3, 4, 5},
                                    {0, 1, 5, 0, 1, 5, 5, 5, 5, 5}};
__constant__ int c_ALSIDE2[2][10] = {{0, 0, 0, 0, 0, 1, 1, 1, 1, 1},
                                     {0, 0, 0, 1, 1, 1, 1, 1, 1, 1}};
__constant__ int c_ALN[2] = {700000, 500000};
__constant__ int c_EPFX2[2][5] = {{0, 100000, 300000, 700000, 1100000},
                                  {0, 100000, 300000, BIG, BIG}};
__constant__ int c_EREL2[2][5] = {{0, 1, 3, 4, 5}, {0, 1, 5, 5, 5}};
__constant__ int c_EN[2] = {1350000, 550000};
__constant__ int c_ACCN[2] = {9600000, 6400000};

struct EdgeParams { const int* src[6]; const int* dst[6]; };

// ---------------- helpers ----------------
__device__ __forceinline__ const float* src_x(int rel) {
    return (rel == 5) ? g_h_post : g_h_user;
}
__device__ __forceinline__ const float* dst_x(int rel) {
    return (rel == 3 || rel == 4) ? g_h_user : g_h_post;
}
__device__ __forceinline__ float* out_acc(int rel) {
    return (rel == 3 || rel == 4) ? g_acc_user : g_acc_post;
}
__device__ __forceinline__ float lrelu(float x) { return x > 0.0f ? x : 0.2f * x; }
__device__ __forceinline__ unsigned int encf(float f) {
    unsigned int u = __float_as_uint(f);
    return (u & 0x80000000u) ? ~u : (u | 0x80000000u);
}
__device__ __forceinline__ float decf(unsigned int u) {
    return (u & 0x80000000u) ? __uint_as_float(u & 0x7fffffffu) : __uint_as_float(~u);
}

// ---------------- re-aspected GEMM: 8 rows x 4 cols per thread ----------------
// Y[n][m] = sum_k X[n][k]*W[m][k] (+ B[m]).  256 threads, ROWS x M tile, KT=32.
// acc stays 8x4 = 32 regs; each warp covers 64 columns -> W LDS bytes per FFMA
// halved vs the 4-row tile.
template <int K, int M, int ROWS>
__device__ __forceinline__ void gemm2(const float* __restrict__ X,
                                      const float* __restrict__ W,
                                      const float* __restrict__ B,
                                      float* __restrict__ Y, int N, int n0)
{
    constexpr int XR = ROWS + 4;
    constexpr int WR = M + 4;
    constexpr int XNF = (ROWS == 128) ? 16 : 8;   // X floats staged per thread
    constexpr int WNF = (M == 128) ? 16 : 8;      // W floats staged per thread
    __shared__ float Xs[32 * XR];
    __shared__ float Ws[32 * WR];

    const int t = threadIdx.x;
    const int tx = t & 15;
    int col0, row0;
    if (M == 128) { col0 = (t >> 7) * 64 + tx * 4; row0 = ((t >> 4) & 7) * 8; }
    else          { col0 = tx * 4;                 row0 = (t >> 4) * 8; }

    const int xn  = (ROWS == 128) ? (t & 127) : (t & 63);
    const int xk0 = (ROWS == 128) ? ((t >> 7) * 16) : ((t >> 6) * 8);
    const int wm  = (M == 128) ? (t & 127) : (t & 63);
    const int wk0 = (M == 128) ? ((t >> 7) * 16) : ((t >> 6) * 8);

    float acc[8][4];
#pragma unroll
    for (int i = 0; i < 8; i++)
#pragma unroll
        for (int j = 0; j < 4; j++) acc[i][j] = 0.0f;

    const bool xok = (n0 + xn) < N;

    for (int k0 = 0; k0 < K; k0 += 32) {
        float4 xr[XNF / 4];
#pragma unroll
        for (int j = 0; j < XNF / 4; j++) xr[j] = make_float4(0.f, 0.f, 0.f, 0.f);
        if (xok) {
            const float4* g = reinterpret_cast<const float4*>(
                X + (size_t)(n0 + xn) * K + k0 + xk0);
#pragma unroll
            for (int j = 0; j < XNF / 4; j++) xr[j] = g[j];
        }
        float4 wr[WNF / 4];
        {
            const float4* g = reinterpret_cast<const float4*>(
                W + (size_t)wm * K + k0 + wk0);
#pragma unroll
            for (int j = 0; j < WNF / 4; j++) wr[j] = g[j];
        }
        __syncthreads();   // previous tile fully consumed
#pragma unroll
        for (int j = 0; j < XNF / 4; j++) {
            Xs[(xk0 + 4 * j + 0) * XR + xn] = xr[j].x;
            Xs[(xk0 + 4 * j + 1) * XR + xn] = xr[j].y;
            Xs[(xk0 + 4 * j + 2) * XR + xn] = xr[j].z;
            Xs[(xk0 + 4 * j + 3) * XR + xn] = xr[j].w;
        }
#pragma unroll
        for (int j = 0; j < WNF / 4; j++) {
            Ws[(wk0 + 4 * j + 0) * WR + wm] = wr[j].x;
            Ws[(wk0 + 4 * j + 1) * WR + wm] = wr[j].y;
            Ws[(wk0 + 4 * j + 2) * WR + wm] = wr[j].z;
            Ws[(wk0 + 4 * j + 3) * WR + wm] = wr[j].w;
        }
        __syncthreads();

#pragma unroll
        for (int kk = 0; kk < 32; kk++) {
            float4 xa = *reinterpret_cast<const float4*>(&Xs[kk * XR + row0]);
            float4 xb = *reinterpret_cast<const float4*>(&Xs[kk * XR + row0 + 4]);
            float4 w4 = *reinterpret_cast<const float4*>(&Ws[kk * WR + col0]);
            float xv[8] = {xa.x, xa.y, xa.z, xa.w, xb.x, xb.y, xb.z, xb.w};
            float wv[4] = {w4.x, w4.y, w4.z, w4.w};
#pragma unroll
            for (int i = 0; i < 8; i++)
#pragma unroll
                for (int j = 0; j < 4; j++)
                    acc[i][j] = fmaf(xv[i], wv[j], acc[i][j]);
        }
        __syncthreads();
    }

    float bj[4];
#pragma unroll
    for (int j = 0; j < 4; j++) bj[j] = B ? B[col0 + j] : 0.0f;
#pragma unroll
    for (int i = 0; i < 8; i++) {
        int n = n0 + row0 + i;
        if (n < N) {
            float4 v;
            v.x = acc[i][0] + bj[0];
            v.y = acc[i][1] + bj[1];
            v.z = acc[i][2] + bj[2];
            v.w = acc[i][3] + bj[3];
            *reinterpret_cast<float4*>(Y + (size_t)n * M + col0) = v;
        }
    }
}

// ---------------- standalone projection kernels ----------------
__global__ void __launch_bounds__(256) proj_post_k(const float* X, const float* W, const float* B) {
    gemm2<768, 64, 128>(X, W, B, g_h_post, NPOST, blockIdx.x * 128);
}
__global__ void __launch_bounds__(256) proj_user_k(const float* X, const float* W, const float* B) {
    gemm2<32, 64, 128>(X, W, B, g_h_user, NUSER, blockIdx.x * 128);
}

// folded attention vectors; also zeroes g_smax for both layers.
__global__ void u_k(const float* __restrict__ Ws, const float* __restrict__ Wd,
                    const float* __restrict__ as_, const float* __restrict__ ad_) {
    int id = blockIdx.x * 256 + threadIdx.x;
    if (blockIdx.x == 0 && threadIdx.x < 24) g_smax[threadIdx.x] = 0u;
    if (id >= 3072) return;
    int k = id & 63, h = (id >> 6) & 1, side = (id >> 7) & 1, rl = id >> 8;
    const float* a = (side ? ad_ : as_) + (size_t)rl * 128 + h * 64;
    const float* W = (side ? Wd : Ws) + (size_t)rl * 8192 + (size_t)h * 64 * 64;
    float u = 0.0f;
#pragma unroll 8
    for (int c = 0; c < 64; c++) u = fmaf(a[c], W[c * 64 + k], u);
    g_u[id] = u;
}

// ---------------- fused stage A: hs GEMMs | al scalars | reset ----------------
__global__ void __launch_bounds__(256) stage_a_k(const float* __restrict__ Wsrc,
                                                 const float* __restrict__ gb,
                                                 int l, int nhs, int nalb) {
    int b = blockIdx.x;
    if (b < nhs) {
        int idx = 0;
#pragma unroll
        for (int r = 1; r < 5; r++) if (b >= c_HSBLK2[l][r]) idx = r;
        int rel = c_HSREL2[l][idx];
        gemm2<64, 128, 64>(src_x(rel), Wsrc + ((size_t)l * 6 + rel) * 8192, nullptr,
                           g_hs + c_HSOFF[rel], c_NSRC[rel],
                           (b - c_HSBLK2[l][idx]) * 64);
        return;
    }
    if (b < nhs + nalb) {
        __shared__ unsigned int s_max[12];
        if (threadIdx.x < 12) s_max[threadIdx.x] = 0u;
        __syncthreads();
        int gid = (b - nhs) * 256 + threadIdx.x;
        if (gid < c_ALN[l]) {
            int t = 0;
#pragma unroll
            for (int i = 1; i < 10; i++) if (gid >= c_ALPFX2[l][i]) t = i;
            int n = gid - c_ALPFX2[l][t];
            int rel = c_ALREL2[l][t];
            int side = c_ALSIDE2[l][t];
            const float* xr = (side ? dst_x(rel) : src_x(rel)) + (size_t)n * 64;
            const float4* x4 = reinterpret_cast<const float4*>(xr);
            const float4* u4 = reinterpret_cast<const float4*>(
                g_u + ((size_t)(l * 6 + rel) * 2 + side) * 128);
            float a0 = 0.0f, a1 = 0.0f;
#pragma unroll
            for (int k = 0; k < 16; k++) {
                float4 xv = x4[k], u0 = u4[k], u1 = u4[16 + k];
                a0 = fmaf(xv.x, u0.x, fmaf(xv.y, u0.y, fmaf(xv.z, u0.z, fmaf(xv.w, u0.w, a0))));
                a1 = fmaf(xv.x, u1.x, fmaf(xv.y, u1.y, fmaf(xv.z, u1.z, fmaf(xv.w, u1.w, a1))));
            }
            float2 r; r.x = a0; r.y = a1;
            if (side) {
                g_al_d[c_DOFF[rel] + n] = r;
            } else {
                g_al_s[c_SOFF[rel] + n] = r;
                atomicMax(&s_max[rel * 2 + 0], encf(a0));
                atomicMax(&s_max[rel * 2 + 1], encf(a1));
            }
        }
        __syncthreads();
        if (threadIdx.x < 12 && s_max[threadIdx.x] != 0u)
            atomicMax(&g_smax[l * 12 + threadIdx.x], s_max[threadIdx.x]);
        return;
    }
    int gid = (b - nhs - nalb) * 256 + threadIdx.x;
    if (gid >= c_ACCN[l]) return;
    if (gid < NDST_TOT * 2) g_ss[gid] = 0.0f;
    int c = gid & 63;
    const float* bb = gb + l * 384;
    if (gid < NPOST * 64)
        g_acc_post[gid] = bb[0 * 64 + c] + bb[1 * 64 + c] + bb[5 * 64 + c];
    else
        g_acc_user[gid - NPOST * 64] = bb[3 * 64 + c] + bb[4 * 64 + c];
}

// stable-softmax numerators using the per-relation src-max upper bound
__global__ void __launch_bounds__(256) edge_sum_k(EdgeParams p, int l) {
    int gid = blockIdx.x * 256 + threadIdx.x;
    if (gid >= c_EN[l]) return;
    int idx = 0;
#pragma unroll
    for (int r = 1; r < 5; r++) if (gid >= c_EPFX2[l][r]) idx = r;
    int rel = c_EREL2[l][idx];
    int e = gid - c_EPFX2[l][idx];
    int s = p.src[rel][e], d = p.dst[rel][e];
    float2 as = g_al_s[c_SOFF[rel] + s];
    float2 ad = g_al_d[c_DOFF[rel] + d];
    float sm0 = decf(g_smax[l * 12 + rel * 2 + 0]);
    float sm1 = decf(g_smax[l * 12 + rel * 2 + 1]);
    float e0 = lrelu(as.x + ad.x);
    float e1 = lrelu(as.y + ad.y);
    float m0 = lrelu(sm0 + ad.x);
    float m1 = lrelu(sm1 + ad.y);
    int di = (c_DOFF[rel] + d) * 2;
    float p0 = __expf(e0 - m0);
    float p1 = __expf(e1 - m1);
    atomicAdd(&g_ss[di + 0], p0);
    atomicAdd(&g_ss[di + 1], p1);
    float2 pr; pr.x = p0; pr.y = p1;
    g_p[gid] = pr;
}

// invert ALL denominators in place (ss is indexed by (DOFF+d)*2 — rel 5 lives
// at [640000,840000); do NOT truncate this range), folding head-mean 0.5x
__global__ void inv_k() {
    int gid = blockIdx.x * 256 + threadIdx.x;
    if (gid >= NDST_TOT * 2) return;
    g_ss[gid] = 0.5f / (g_ss[gid] + 1e-16f);
}

// 16 threads per edge, 4 channels each; single float4 vector atomic per thread
__global__ void __launch_bounds__(256) edge_msg_k(EdgeParams p, int l) {
    int gid = blockIdx.x * 256 + threadIdx.x;
    int e = gid >> 4, c0 = (gid & 15) << 2;
    if (e >= c_EN[l]) return;
    int idx = 0;
#pragma unroll
    for (int r = 1; r < 5; r++) if (e >= c_EPFX2[l][r]) idx = r;
    int rel = c_EREL2[l][idx];
    int eloc = e - c_EPFX2[l][idx];
    int s = p.src[rel][eloc], d = p.dst[rel][eloc];
    float2 pr = g_p[e];
    int di = (c_DOFF[rel] + d) * 2;
    float a0 = pr.x * g_ss[di + 0];
    float a1 = pr.y * g_ss[di + 1];
    const float* hsrow = g_hs + c_HSOFF[rel] + (size_t)s * 128;
    float4 h0 = *reinterpret_cast<const float4*>(hsrow + c0);
    float4 h1 = *reinterpret_cast<const float4*>(hsrow + 64 + c0);
    float4 v;
    v.x = a0 * h0.x + a1 * h1.x;
    v.y = a0 * h0.y + a1 * h1.y;
    v.z = a0 * h0.z + a1 * h1.z;
    v.w = a0 * h0.w + a1 * h1.w;
    float4* acc = reinterpret_cast<float4*>(out_acc(rel) + (size_t)d * 64 + c0);
    atomicAdd(acc, v);
}

// layer-0 relu: post + user only
__global__ void relu_k() {
    int gid = blockIdx.x * 256 + threadIdx.x;
    if (gid >= 9600000) return;
    if (gid < NPOST * 64)
        g_h_post[gid] = fmaxf(g_acc_post[gid], 0.0f);
    else {
        int i = gid - NPOST * 64;
        g_h_user[i] = fmaxf(g_acc_user[i], 0.0f);
    }
}

// classifier: one warp per post node; layer-2 relu folded into the load
__global__ void __launch_bounds__(256) cls_k(const float* __restrict__ w1,
                                             const float* __restrict__ b1,
                                             const float* __restrict__ w2,
                                             const float* __restrict__ b2,
                                             float* __restrict__ out) {
    int gid = blockIdx.x * 256 + threadIdx.x;
    int n = gid >> 5, lane = gid & 31;
    if (n >= NPOST) return;
    const float4* x4 = reinterpret_cast<const float4*>(g_acc_post + (size_t)n * 64);
    const float4* w4 = reinterpret_cast<const float4*>(w1 + (size_t)lane * 64);
    float a = 0.0f;
#pragma unroll
    for (int k = 0; k < 16; k++) {
        float4 xv = x4[k], wv = w4[k];
        xv.x = fmaxf(xv.x, 0.0f); xv.y = fmaxf(xv.y, 0.0f);
        xv.z = fmaxf(xv.z, 0.0f); xv.w = fmaxf(xv.w, 0.0f);
        a = fmaf(xv.x, wv.x, fmaf(xv.y, wv.y, fmaf(xv.z, wv.z, fmaf(xv.w, wv.w, a))));
    }
    float h = fmaxf(a + b1[lane], 0.0f) * w2[lane];
#pragma unroll
    for (int off = 16; off > 0; off >>= 1)
        h += __shfl_xor_sync(0xffffffffu, h, off);
    if (lane == 0) out[n] = h + b2[0];
}

// ---------------- launch ----------------
extern "C" void kernel_launch(void* const* d_in, const int* in_sizes, int n_in,
                              void* d_out, int out_size) {
    const float* x_post = (const float*)d_in[0];
    const float* x_user = (const float*)d_in[1];
    EdgeParams ep;
    for (int r = 0; r < 6; r++) {
        ep.src[r] = (const int*)d_in[3 + 2 * r];
        ep.dst[r] = (const int*)d_in[4 + 2 * r];
    }
    const float* post_w = (const float*)d_in[15];
    const float* post_b = (const float*)d_in[16];
    const float* user_w = (const float*)d_in[17];
    const float* user_b = (const float*)d_in[18];
    const float* W_src  = (const float*)d_in[21];
    const float* W_dst  = (const float*)d_in[22];
    const float* a_src  = (const float*)d_in[23];
    const float* a_dst  = (const float*)d_in[24];
    const float* gat_b  = (const float*)d_in[25];
    const float* cls_w1 = (const float*)d_in[26];
    const float* cls_b1 = (const float*)d_in[27];
    const float* cls_w2 = (const float*)d_in[28];
    const float* cls_b2 = (const float*)d_in[29];
    float* out = (float*)d_out;

    proj_post_k<<<782, 256>>>(x_post, post_w, post_b);
    proj_user_k<<<391, 256>>>(x_user, user_w, user_b);
    u_k<<<12, 256>>>(W_src, W_dst, a_src, a_dst);

    // layer 0: rels {0,1,3,4,5}
    stage_a_k<<<4691 + 2735 + 37500, 256>>>(W_src, gat_b, 0, 4691, 2735);
    edge_sum_k<<<5274, 256>>>(ep, 0);
    inv_k<<<3282, 256>>>();
    edge_msg_k<<<84375, 256>>>(ep, 0);
    relu_k<<<37500, 256>>>();

    // layer 1: rels {0,1,5}
    stage_a_k<<<3127 + 1954 + 25000, 256>>>(W_src, gat_b, 1, 3127, 1954);
    edge_sum_k<<<2149, 256>>>(ep, 1);
    inv_k<<<3282, 256>>>();
    edge_msg_k<<<34375, 256>>>(ep, 1);

    cls_k<<<12500, 256>>>(cls_w1, cls_b1, cls_w2, cls_b2, out);
}

// round 13
// speedup vs baseline: 2.3817x; 1.0037x over previous
#include <cuda_runtime.h>
#include <cuda_bf16.h>
#include <cstdint>

#define NPOST 100000
#define NUSER 50000
#define NSRC_TOT 400000
#define NDST_TOT 420000
#define BIG (1 << 29)

// ---------------- static device scratch ----------------
__device__ float g_h_post[NPOST * 64];
__device__ float g_h_user[NUSER * 64];
__device__ float g_acc_post[NPOST * 64];
__device__ float g_acc_user[NUSER * 64];
__device__ float g_hs[51200000];        // concat per-relation hs [N_src][128]
__device__ float2 g_al_s[NSRC_TOT];
__device__ float2 g_al_d[NDST_TOT];
__device__ float        g_ss[NDST_TOT * 2]; // softmax denom -> inverted in place
__device__ float2 g_p[1350000];             // unnormalized softmax numerators
__device__ float g_u[3072];             // folded attention vectors [l][r][side][h][64]
__device__ unsigned int g_smax[24];     // encoded per-(layer,rel,head) max of al_s

// ---------------- constant tables ----------------
__constant__ int c_SOFF[6]  = {0, 50000, 100000, 200000, 250000, 300000};
__constant__ int c_DOFF[6]  = {0, 100000, 200000, 220000, 270000, 320000};
__constant__ int c_HSOFF[6] = {0, 6400000, 12800000, 25600000, 32000000, 38400000};
__constant__ int c_NSRC[6]  = {50000, 50000, 100000, 50000, 50000, 100000};

// per-layer live-relation dispatch (ent + rel2 dead; layer1 post rels only)
// hs blocks of 128 nodes: NSRC 50k -> 391 blocks, 100k -> 782 blocks
__constant__ int c_HSBLK2[2][5] = {{0, 391, 782, 1173, 1564},
                                   {0, 391, 782, BIG, BIG}};
__constant__ int c_HSREL2[2][5] = {{0, 1, 3, 4, 5}, {0, 1, 5, 5, 5}};
__constant__ int c_ALPFX2[2][10] = {
    {0, 50000, 100000, 150000, 200000, 300000, 400000, 500000, 550000, 600000},
    {0, 50000, 100000, 200000, 300000, 400000, BIG, BIG, BIG, BIG}};
__constant__ int c_ALREL2[2][10] = {{0, 1, 3, 4, 5, 0, 1, 3, 4, 5},
                                    {0, 1, 5, 0, 1, 5, 5, 5, 5, 5}};
__constant__ int c_ALSIDE2[2][10] = {{0, 0, 0, 0, 0, 1, 1, 1, 1, 1},
                                     {0, 0, 0, 1, 1, 1, 1, 1, 1, 1}};
__constant__ int c_ALN[2] = {700000, 500000};
__constant__ int c_EPFX2[2][5] = {{0, 100000, 300000, 700000, 1100000},
                                  {0, 100000, 300000, BIG, BIG}};
__constant__ int c_EREL2[2][5] = {{0, 1, 3, 4, 5}, {0, 1, 5, 5, 5}};
__constant__ int c_EN[2] = {1350000, 550000};
__constant__ int c_ACCN[2] = {9600000, 6400000};

struct EdgeParams { const int* src[6]; const int* dst[6]; };

// ---------------- helpers ----------------
__device__ __forceinline__ const float* src_x(int rel) {
    return (rel == 5) ? g_h_post : g_h_user;
}
__device__ __forceinline__ const float* dst_x(int rel) {
    return (rel == 3 || rel == 4) ? g_h_user : g_h_post;
}
__device__ __forceinline__ float* out_acc(int rel) {
    return (rel == 3 || rel == 4) ? g_acc_user : g_acc_post;
}
__device__ __forceinline__ float lrelu(float x) { return x > 0.0f ? x : 0.2f * x; }
__device__ __forceinline__ unsigned int encf(float f) {
    unsigned int u = __float_as_uint(f);
    return (u & 0x80000000u) ? ~u : (u | 0x80000000u);
}
__device__ __forceinline__ float decf(unsigned int u) {
    return (u & 0x80000000u) ? __uint_as_float(u & 0x7fffffffu) : __uint_as_float(~u);
}

// ---------------- 8x8-tile GEMM: Y[n][m] = sum_k X[n][k]*W[m][k] (+ B[m]) ----------------
// 256 threads, ROWS x M block tile (ROWS*M = 16384), KT=32.
// Per-thread 8 rows x 8 cols; the 8 cols are split as {cg*4..+3, cg*4+M/2..+3}
// -> every LDS.128 group is 16B-strided across the warp: conflict-free, no
// round-8 4-way W conflict. 4 LDS.128 feed 64 FFMA (2x better than 8x4 tile).
template <int K, int M, int ROWS>
__device__ __forceinline__ void gemm3(const float* __restrict__ X,
                                      const float* __restrict__ W,
                                      const float* __restrict__ B,
                                      float* __restrict__ Y, int N, int n0)
{
    constexpr int XR = ROWS + 4;
    constexpr int WR = M + 4;
    constexpr int CG = M / 8;                     // col groups (8 or 16)
    constexpr int CH = M / 2;                     // column-half offset
    constexpr int XNF = (ROWS == 256) ? 32 : 16;  // X floats staged per thread
    constexpr int WNF = (M == 64) ? 8 : 16;       // W floats staged per thread
    __shared__ float Xs[32 * XR];
    __shared__ float Ws[32 * WR];

    const int t = threadIdx.x;
    const int cg = t % CG, rg = t / CG;
    const int col0 = cg * 4;
    const int row0 = rg * 8;

    const int xn  = (ROWS == 256) ? t : (t & 127);
    const int xk0 = (ROWS == 256) ? 0 : ((t >> 7) * 16);
    const int wm  = (M == 64) ? (t & 63) : (t & 127);
    const int wk0 = (M == 64) ? ((t >> 6) * 8) : ((t >> 7) * 16);

    float acc[8][8];
#pragma unroll
    for (int i = 0; i < 8; i++)
#pragma unroll
        for (int j = 0; j < 8; j++) acc[i][j] = 0.0f;

    const bool xok = (n0 + xn) < N;

    for (int k0 = 0; k0 < K; k0 += 32) {
        float4 xr[XNF / 4];
#pragma unroll
        for (int j = 0; j < XNF / 4; j++) xr[j] = make_float4(0.f, 0.f, 0.f, 0.f);
        if (xok) {
            const float4* g = reinterpret_cast<const float4*>(
                X + (size_t)(n0 + xn) * K + k0 + xk0);
#pragma unroll
            for (int j = 0; j < XNF / 4; j++) xr[j] = g[j];
        }
        float4 wr[WNF / 4];
        {
            const float4* g = reinterpret_cast<const float4*>(
                W + (size_t)wm * K + k0 + wk0);
#pragma unroll
            for (int j = 0; j < WNF / 4; j++) wr[j] = g[j];
        }
        __syncthreads();   // previous tile fully consumed
#pragma unroll
        for (int j = 0; j < XNF / 4; j++) {
            Xs[(xk0 + 4 * j + 0) * XR + xn] = xr[j].x;
            Xs[(xk0 + 4 * j + 1) * XR + xn] = xr[j].y;
            Xs[(xk0 + 4 * j + 2) * XR + xn] = xr[j].z;
            Xs[(xk0 + 4 * j + 3) * XR + xn] = xr[j].w;
        }
#pragma unroll
        for (int j = 0; j < WNF / 4; j++) {
            Ws[(wk0 + 4 * j + 0) * WR + wm] = wr[j].x;
            Ws[(wk0 + 4 * j + 1) * WR + wm] = wr[j].y;
            Ws[(wk0 + 4 * j + 2) * WR + wm] = wr[j].z;
            Ws[(wk0 + 4 * j + 3) * WR + wm] = wr[j].w;
        }
        __syncthreads();

#pragma unroll
        for (int kk = 0; kk < 32; kk++) {
            float4 xa = *reinterpret_cast<const float4*>(&Xs[kk * XR + row0]);
            float4 xb = *reinterpret_cast<const float4*>(&Xs[kk * XR + row0 + 4]);
            float4 wa = *reinterpret_cast<const float4*>(&Ws[kk * WR + col0]);
            float4 wb = *reinterpret_cast<const float4*>(&Ws[kk * WR + col0 + CH]);
            float xv[8] = {xa.x, xa.y, xa.z, xa.w, xb.x, xb.y, xb.z, xb.w};
            float wv[8] = {wa.x, wa.y, wa.z, wa.w, wb.x, wb.y, wb.z, wb.w};
#pragma unroll
            for (int i = 0; i < 8; i++)
#pragma unroll
                for (int j = 0; j < 8; j++)
                    acc[i][j] = fmaf(xv[i], wv[j], acc[i][j]);
        }
        __syncthreads();
    }

    float bj[8];
#pragma unroll
    for (int j = 0; j < 4; j++) {
        bj[j]     = B ? B[col0 + j]      : 0.0f;
        bj[4 + j] = B ? B[col0 + CH + j] : 0.0f;
    }
#pragma unroll
    for (int i = 0; i < 8; i++) {
        int n = n0 + row0 + i;
        if (n < N) {
            float4 v0, v1;
            v0.x = acc[i][0] + bj[0]; v0.y = acc[i][1] + bj[1];
            v0.z = acc[i][2] + bj[2]; v0.w = acc[i][3] + bj[3];
            v1.x = acc[i][4] + bj[4]; v1.y = acc[i][5] + bj[5];
            v1.z = acc[i][6] + bj[6]; v1.w = acc[i][7] + bj[7];
            *reinterpret_cast<float4*>(Y + (size_t)n * M + col0)      = v0;
            *reinterpret_cast<float4*>(Y + (size_t)n * M + col0 + CH) = v1;
        }
    }
}

// ---------------- standalone projection kernels ----------------
__global__ void __launch_bounds__(256) proj_post_k(const float* X, const float* W, const float* B) {
    gemm3<768, 64, 256>(X, W, B, g_h_post, NPOST, blockIdx.x * 256);
}
__global__ void __launch_bounds__(256) proj_user_k(const float* X, const float* W, const float* B) {
    gemm3<32, 64, 256>(X, W, B, g_h_user, NUSER, blockIdx.x * 256);
}

// folded attention vectors; also zeroes g_smax for both layers.
__global__ void u_k(const float* __restrict__ Ws, const float* __restrict__ Wd,
                    const float* __restrict__ as_, const float* __restrict__ ad_) {
    int id = blockIdx.x * 256 + threadIdx.x;
    if (blockIdx.x == 0 && threadIdx.x < 24) g_smax[threadIdx.x] = 0u;
    if (id >= 3072) return;
    int k = id & 63, h = (id >> 6) & 1, side = (id >> 7) & 1, rl = id >> 8;
    const float* a = (side ? ad_ : as_) + (size_t)rl * 128 + h * 64;
    const float* W = (side ? Wd : Ws) + (size_t)rl * 8192 + (size_t)h * 64 * 64;
    float u = 0.0f;
#pragma unroll 8
    for (int c = 0; c < 64; c++) u = fmaf(a[c], W[c * 64 + k], u);
    g_u[id] = u;
}

// ---------------- fused stage A: hs GEMMs | al scalars | reset ----------------
__global__ void __launch_bounds__(256) stage_a_k(const float* __restrict__ Wsrc,
                                                 const float* __restrict__ gb,
                                                 int l, int nhs, int nalb) {
    int b = blockIdx.x;
    if (b < nhs) {
        int idx = 0;
#pragma unroll
        for (int r = 1; r < 5; r++) if (b >= c_HSBLK2[l][r]) idx = r;
        int rel = c_HSREL2[l][idx];
        gemm3<64, 128, 128>(src_x(rel), Wsrc + ((size_t)l * 6 + rel) * 8192, nullptr,
                            g_hs + c_HSOFF[rel], c_NSRC[rel],
                            (b - c_HSBLK2[l][idx]) * 128);
        return;
    }
    if (b < nhs + nalb) {
        __shared__ unsigned int s_max[12];
        if (threadIdx.x < 12) s_max[threadIdx.x] = 0u;
        __syncthreads();
        int gid = (b - nhs) * 256 + threadIdx.x;
        if (gid < c_ALN[l]) {
            int t = 0;
#pragma unroll
            for (int i = 1; i < 10; i++) if (gid >= c_ALPFX2[l][i]) t = i;
            int n = gid - c_ALPFX2[l][t];
            int rel = c_ALREL2[l][t];
            int side = c_ALSIDE2[l][t];
            const float* xr = (side ? dst_x(rel) : src_x(rel)) + (size_t)n * 64;
            const float4* x4 = reinterpret_cast<const float4*>(xr);
            const float4* u4 = reinterpret_cast<const float4*>(
                g_u + ((size_t)(l * 6 + rel) * 2 + side) * 128);
            float a0 = 0.0f, a1 = 0.0f;
#pragma unroll
            for (int k = 0; k < 16; k++) {
                float4 xv = x4[k], u0 = u4[k], u1 = u4[16 + k];
                a0 = fmaf(xv.x, u0.x, fmaf(xv.y, u0.y, fmaf(xv.z, u0.z, fmaf(xv.w, u0.w, a0))));
                a1 = fmaf(xv.x, u1.x, fmaf(xv.y, u1.y, fmaf(xv.z, u1.z, fmaf(xv.w, u1.w, a1))));
            }
            float2 r; r.x = a0; r.y = a1;
            if (side) {
                g_al_d[c_DOFF[rel] + n] = r;
            } else {
                g_al_s[c_SOFF[rel] + n] = r;
                atomicMax(&s_max[rel * 2 + 0], encf(a0));
                atomicMax(&s_max[rel * 2 + 1], encf(a1));
            }
        }
        __syncthreads();
        if (threadIdx.x < 12 && s_max[threadIdx.x] != 0u)
            atomicMax(&g_smax[l * 12 + threadIdx.x], s_max[threadIdx.x]);
        return;
    }
    int gid = (b - nhs - nalb) * 256 + threadIdx.x;
    if (gid >= c_ACCN[l]) return;
    if (gid < NDST_TOT * 2) g_ss[gid] = 0.0f;
    int c = gid & 63;
    const float* bb = gb + l * 384;
    if (gid < NPOST * 64)
        g_acc_post[gid] = bb[0 * 64 + c] + bb[1 * 64 + c] + bb[5 * 64 + c];
    else
        g_acc_user[gid - NPOST * 64] = bb[3 * 64 + c] + bb[4 * 64 + c];
}

// stable-softmax numerators using the per-relation src-max upper bound
__global__ void __launch_bounds__(256) edge_sum_k(EdgeParams p, int l) {
    int gid = blockIdx.x * 256 + threadIdx.x;
    if (gid >= c_EN[l]) return;
    int idx = 0;
#pragma unroll
    for (int r = 1; r < 5; r++) if (gid >= c_EPFX2[l][r]) idx = r;
    int rel = c_EREL2[l][idx];
    int e = gid - c_EPFX2[l][idx];
    int s = p.src[rel][e], d = p.dst[rel][e];
    float2 as = g_al_s[c_SOFF[rel] + s];
    float2 ad = g_al_d[c_DOFF[rel] + d];
    float sm0 = decf(g_smax[l * 12 + rel * 2 + 0]);
    float sm1 = decf(g_smax[l * 12 + rel * 2 + 1]);
    float e0 = lrelu(as.x + ad.x);
    float e1 = lrelu(as.y + ad.y);
    float m0 = lrelu(sm0 + ad.x);
    float m1 = lrelu(sm1 + ad.y);
    int di = (c_DOFF[rel] + d) * 2;
    float p0 = __expf(e0 - m0);
    float p1 = __expf(e1 - m1);
    atomicAdd(&g_ss[di + 0], p0);
    atomicAdd(&g_ss[di + 1], p1);
    float2 pr; pr.x = p0; pr.y = p1;
    g_p[gid] = pr;
}

// invert ALL denominators in place (ss is indexed by (DOFF+d)*2 — rel 5 lives
// at [640000,840000); do NOT truncate this range), folding head-mean 0.5x
__global__ void inv_k() {
    int gid = blockIdx.x * 256 + threadIdx.x;
    if (gid >= NDST_TOT * 2) return;
    g_ss[gid] = 0.5f / (g_ss[gid] + 1e-16f);
}

// 16 threads per edge, 4 channels each; single float4 vector atomic per thread
__global__ void __launch_bounds__(256) edge_msg_k(EdgeParams p, int l) {
    int gid = blockIdx.x * 256 + threadIdx.x;
    int e = gid >> 4, c0 = (gid & 15) << 2;
    if (e >= c_EN[l]) return;
    int idx = 0;
#pragma unroll
    for (int r = 1; r < 5; r++) if (e >= c_EPFX2[l][r]) idx = r;
    int rel = c_EREL2[l][idx];
    int eloc = e - c_EPFX2[l][idx];
    int s = p.src[rel][eloc], d = p.dst[rel][eloc];
    float2 pr = g_p[e];
    int di = (c_DOFF[rel] + d) * 2;
    float a0 = pr.x * g_ss[di + 0];
    float a1 = pr.y * g_ss[di + 1];
    const float* hsrow = g_hs + c_HSOFF[rel] + (size_t)s * 128;
    float4 h0 = *reinterpret_cast<const float4*>(hsrow + c0);
    float4 h1 = *reinterpret_cast<const float4*>(hsrow + 64 + c0);
    float4 v;
    v.x = a0 * h0.x + a1 * h1.x;
    v.y = a0 * h0.y + a1 * h1.y;
    v.z = a0 * h0.z + a1 * h1.z;
    v.w = a0 * h0.w + a1 * h1.w;
    float4* acc = reinterpret_cast<float4*>(out_acc(rel) + (size_t)d * 64 + c0);
    atomicAdd(acc, v);
}

// layer-0 relu: post + user only
__global__ void relu_k() {
    int gid = blockIdx.x * 256 + threadIdx.x;
    if (gid >= 9600000) return;
    if (gid < NPOST * 64)
        g_h_post[gid] = fmaxf(g_acc_post[gid], 0.0f);
    else {
        int i = gid - NPOST * 64;
        g_h_user[i] = fmaxf(g_acc_user[i], 0.0f);
    }
}

// classifier: one warp per post node; layer-2 relu folded into the load
__global__ void __launch_bounds__(256) cls_k(const float* __restrict__ w1,
                                             const float* __restrict__ b1,
                                             const float* __restrict__ w2,
                                             const float* __restrict__ b2,
                                             float* __restrict__ out) {
    int gid = blockIdx.x * 256 + threadIdx.x;
    int n = gid >> 5, lane = gid & 31;
    if (n >= NPOST) return;
    const float4* x4 = reinterpret_cast<const float4*>(g_acc_post + (size_t)n * 64);
    const float4* w4 = reinterpret_cast<const float4*>(w1 + (size_t)lane * 64);
    float a = 0.0f;
#pragma unroll
    for (int k = 0; k < 16; k++) {
        float4 xv = x4[k], wv = w4[k];
        xv.x = fmaxf(xv.x, 0.0f); xv.y = fmaxf(xv.y, 0.0f);
        xv.z = fmaxf(xv.z, 0.0f); xv.w = fmaxf(xv.w, 0.0f);
        a = fmaf(xv.x, wv.x, fmaf(xv.y, wv.y, fmaf(xv.z, wv.z, fmaf(xv.w, wv.w, a))));
    }
    float h = fmaxf(a + b1[lane], 0.0f) * w2[lane];
#pragma unroll
    for (int off = 16; off > 0; off >>= 1)
        h += __shfl_xor_sync(0xffffffffu, h, off);
    if (lane == 0) out[n] = h + b2[0];
}

// ---------------- launch ----------------
extern "C" void kernel_launch(void* const* d_in, const int* in_sizes, int n_in,
                              void* d_out, int out_size) {
    const float* x_post = (const float*)d_in[0];
    const float* x_user = (const float*)d_in[1];
    EdgeParams ep;
    for (int r = 0; r < 6; r++) {
        ep.src[r] = (const int*)d_in[3 + 2 * r];
        ep.dst[r] = (const int*)d_in[4 + 2 * r];
    }
    const float* post_w = (const float*)d_in[15];
    const float* post_b = (const float*)d_in[16];
    const float* user_w = (const float*)d_in[17];
    const float* user_b = (const float*)d_in[18];
    const float* W_src  = (const float*)d_in[21];
    const float* W_dst  = (const float*)d_in[22];
    const float* a_src  = (const float*)d_in[23];
    const float* a_dst  = (const float*)d_in[24];
    const float* gat_b  = (const float*)d_in[25];
    const float* cls_w1 = (const float*)d_in[26];
    const float* cls_b1 = (const float*)d_in[27];
    const float* cls_w2 = (const float*)d_in[28];
    const float* cls_b2 = (const float*)d_in[29];
    float* out = (float*)d_out;

    proj_post_k<<<391, 256>>>(x_post, post_w, post_b);
    proj_user_k<<<196, 256>>>(x_user, user_w, user_b);
    u_k<<<12, 256>>>(W_src, W_dst, a_src, a_dst);

    // layer 0: rels {0,1,3,4,5}; hs blocks of 128 rows -> 391*4 + 782 = 2346
    stage_a_k<<<2346 + 2735 + 37500, 256>>>(W_src, gat_b, 0, 2346, 2735);
    edge_sum_k<<<5274, 256>>>(ep, 0);
    inv_k<<<3282, 256>>>();
    edge_msg_k<<<84375, 256>>>(ep, 0);
    relu_k<<<37500, 256>>>();

    // layer 1: rels {0,1,5}; hs blocks 391+391+782 = 1564
    stage_a_k<<<1564 + 1954 + 25000, 256>>>(W_src, gat_b, 1, 1564, 1954);
    edge_sum_k<<<2149, 256>>>(ep, 1);
    inv_k<<<3282, 256>>>();
    edge_msg_k<<<34375, 256>>>(ep, 1);

    cls_k<<<12500, 256>>>(cls_w1, cls_b1, cls_w2, cls_b2, out);
}

// round 14
// speedup vs baseline: 2.3854x; 1.0015x over previous
#include <cuda_runtime.h>
#include <cuda_bf16.h>
#include <cstdint>

#define NPOST 100000
#define NUSER 50000
#define NSRC_TOT 400000
#define NDST_TOT 420000
#define BIG (1 << 29)

// ---------------- static device scratch ----------------
__device__ float g_h_post[NPOST * 64];
__device__ float g_h_user[NUSER * 64];
__device__ float g_acc_post[NPOST * 64];
__device__ float g_acc_user[NUSER * 64];
__device__ float g_hs[51200000];        // concat per-relation hs [N_src][128]
__device__ float2 g_al_s[NSRC_TOT];
__device__ float2 g_al_d[NDST_TOT];
__device__ float        g_ss[NDST_TOT * 2]; // softmax denom -> inverted in place
__device__ float2 g_p[1350000];             // unnormalized softmax numerators
__device__ float g_u[3072];             // folded attention vectors [l][r][side][h][64]
__device__ unsigned int g_smax[24];     // encoded per-(layer,rel,head) max of al_s

// ---------------- constant tables ----------------
__constant__ int c_SOFF[6]  = {0, 50000, 100000, 200000, 250000, 300000};
__constant__ int c_DOFF[6]  = {0, 100000, 200000, 220000, 270000, 320000};
__constant__ int c_HSOFF[6] = {0, 6400000, 12800000, 25600000, 32000000, 38400000};
__constant__ int c_NSRC[6]  = {50000, 50000, 100000, 50000, 50000, 100000};

// per-layer live-relation dispatch (ent + rel2 dead; layer1 post rels only)
// hs blocks of 128 nodes: NSRC 50k -> 391 blocks, 100k -> 782 blocks
__constant__ int c_HSBLK2[2][5] = {{0, 391, 782, 1173, 1564},
                                   {0, 391, 782, BIG, BIG}};
__constant__ int c_HSREL2[2][5] = {{0, 1, 3, 4, 5}, {0, 1, 5, 5, 5}};
__constant__ int c_ALPFX2[2][10] = {
    {0, 50000, 100000, 150000, 200000, 300000, 400000, 500000, 550000, 600000},
    {0, 50000, 100000, 200000, 300000, 400000, BIG, BIG, BIG, BIG}};
__constant__ int c_ALREL2[2][10] = {{0, 1, 3, 4, 5, 0, 1, 3, 4, 5},
                                    {0, 1, 5, 0, 1, 5, 5, 5, 5, 5}};
__constant__ int c_ALSIDE2[2][10] = {{0, 0, 0, 0, 0, 1, 1, 1, 1, 1},
                                     {0, 0, 0, 1, 1, 1, 1, 1, 1, 1}};
__constant__ int c_ALN[2] = {700000, 500000};
__constant__ int c_EPFX2[2][5] = {{0, 100000, 300000, 700000, 1100000},
                                  {0, 100000, 300000, BIG, BIG}};
__constant__ int c_EREL2[2][5] = {{0, 1, 3, 4, 5}, {0, 1, 5, 5, 5}};
__constant__ int c_EN[2] = {1350000, 550000};
__constant__ int c_ACCN[2] = {9600000, 6400000};

struct EdgeParams { const int* src[6]; const int* dst[6]; };

// ---------------- helpers ----------------
__device__ __forceinline__ const float* src_x(int rel) {
    return (rel == 5) ? g_h_post : g_h_user;
}
__device__ __forceinline__ const float* dst_x(int rel) {
    return (rel == 3 || rel == 4) ? g_h_user : g_h_post;
}
__device__ __forceinline__ float* out_acc(int rel) {
    return (rel == 3 || rel == 4) ? g_acc_user : g_acc_post;
}
__device__ __forceinline__ float lrelu(float x) { return x > 0.0f ? x : 0.2f * x; }
__device__ __forceinline__ unsigned int encf(float f) {
    unsigned int u = __float_as_uint(f);
    return (u & 0x80000000u) ? ~u : (u | 0x80000000u);
}
__device__ __forceinline__ float decf(unsigned int u) {
    return (u & 0x80000000u) ? __uint_as_float(u & 0x7fffffffu) : __uint_as_float(~u);
}

// ---------------- 8x8-tile GEMM: Y[n][m] = sum_k X[n][k]*W[m][k] (+ B[m]) ----------------
// 256 threads, ROWS x M block tile (ROWS*M = 16384), KT=32.
// Per-thread 8 rows x 8 cols; the 8 cols are split as {cg*4..+3, cg*4+M/2..+3}
// -> every LDS.128 group is 16B-strided across the warp: conflict-free, no
// round-8 4-way W conflict. 4 LDS.128 feed 64 FFMA (2x better than 8x4 tile).
template <int K, int M, int ROWS>
__device__ __forceinline__ void gemm3(const float* __restrict__ X,
                                      const float* __restrict__ W,
                                      const float* __restrict__ B,
                                      float* __restrict__ Y, int N, int n0)
{
    constexpr int XR = ROWS + 4;
    constexpr int WR = M + 4;
    constexpr int CG = M / 8;                     // col groups (8 or 16)
    constexpr int CH = M / 2;                     // column-half offset
    constexpr int XNF = (ROWS == 256) ? 32 : 16;  // X floats staged per thread
    constexpr int WNF = (M == 64) ? 8 : 16;       // W floats staged per thread
    __shared__ float Xs[32 * XR];
    __shared__ float Ws[32 * WR];

    const int t = threadIdx.x;
    const int cg = t % CG, rg = t / CG;
    const int col0 = cg * 4;
    const int row0 = rg * 8;

    const int xn  = (ROWS == 256) ? t : (t & 127);
    const int xk0 = (ROWS == 256) ? 0 : ((t >> 7) * 16);
    const int wm  = (M == 64) ? (t & 63) : (t & 127);
    const int wk0 = (M == 64) ? ((t >> 6) * 8) : ((t >> 7) * 16);

    float acc[8][8];
#pragma unroll
    for (int i = 0; i < 8; i++)
#pragma unroll
        for (int j = 0; j < 8; j++) acc[i][j] = 0.0f;

    const bool xok = (n0 + xn) < N;

    for (int k0 = 0; k0 < K; k0 += 32) {
        float4 xr[XNF / 4];
#pragma unroll
        for (int j = 0; j < XNF / 4; j++) xr[j] = make_float4(0.f, 0.f, 0.f, 0.f);
        if (xok) {
            const float4* g = reinterpret_cast<const float4*>(
                X + (size_t)(n0 + xn) * K + k0 + xk0);
#pragma unroll
            for (int j = 0; j < XNF / 4; j++) xr[j] = g[j];
        }
        float4 wr[WNF / 4];
        {
            const float4* g = reinterpret_cast<const float4*>(
                W + (size_t)wm * K + k0 + wk0);
#pragma unroll
            for (int j = 0; j < WNF / 4; j++) wr[j] = g[j];
        }
        __syncthreads();   // previous tile fully consumed
#pragma unroll
        for (int j = 0; j < XNF / 4; j++) {
            Xs[(xk0 + 4 * j + 0) * XR + xn] = xr[j].x;
            Xs[(xk0 + 4 * j + 1) * XR + xn] = xr[j].y;
            Xs[(xk0 + 4 * j + 2) * XR + xn] = xr[j].z;
            Xs[(xk0 + 4 * j + 3) * XR + xn] = xr[j].w;
        }
#pragma unroll
        for (int j = 0; j < WNF / 4; j++) {
            Ws[(wk0 + 4 * j + 0) * WR + wm] = wr[j].x;
            Ws[(wk0 + 4 * j + 1) * WR + wm] = wr[j].y;
            Ws[(wk0 + 4 * j + 2) * WR + wm] = wr[j].z;
            Ws[(wk0 + 4 * j + 3) * WR + wm] = wr[j].w;
        }
        __syncthreads();

#pragma unroll
        for (int kk = 0; kk < 32; kk++) {
            float4 xa = *reinterpret_cast<const float4*>(&Xs[kk * XR + row0]);
            float4 xb = *reinterpret_cast<const float4*>(&Xs[kk * XR + row0 + 4]);
            float4 wa = *reinterpret_cast<const float4*>(&Ws[kk * WR + col0]);
            float4 wb = *reinterpret_cast<const float4*>(&Ws[kk * WR + col0 + CH]);
            float xv[8] = {xa.x, xa.y, xa.z, xa.w, xb.x, xb.y, xb.z, xb.w};
            float wv[8] = {wa.x, wa.y, wa.z, wa.w, wb.x, wb.y, wb.z, wb.w};
#pragma unroll
            for (int i = 0; i < 8; i++)
#pragma unroll
                for (int j = 0; j < 8; j++)
                    acc[i][j] = fmaf(xv[i], wv[j], acc[i][j]);
        }
        __syncthreads();
    }

    float bj[8];
#pragma unroll
    for (int j = 0; j < 4; j++) {
        bj[j]     = B ? B[col0 + j]      : 0.0f;
        bj[4 + j] = B ? B[col0 + CH + j] : 0.0f;
    }
#pragma unroll
    for (int i = 0; i < 8; i++) {
        int n = n0 + row0 + i;
        if (n < N) {
            float4 v0, v1;
            v0.x = acc[i][0] + bj[0]; v0.y = acc[i][1] + bj[1];
            v0.z = acc[i][2] + bj[2]; v0.w = acc[i][3] + bj[3];
            v1.x = acc[i][4] + bj[4]; v1.y = acc[i][5] + bj[5];
            v1.z = acc[i][6] + bj[6]; v1.w = acc[i][7] + bj[7];
            *reinterpret_cast<float4*>(Y + (size_t)n * M + col0)      = v0;
            *reinterpret_cast<float4*>(Y + (size_t)n * M + col0 + CH) = v1;
        }
    }
}

// ---------------- standalone projection kernels ----------------
__global__ void __launch_bounds__(256) proj_post_k(const float* X, const float* W, const float* B) {
    gemm3<768, 64, 256>(X, W, B, g_h_post, NPOST, blockIdx.x * 256);
}
__global__ void __launch_bounds__(256) proj_user_k(const float* X, const float* W, const float* B) {
    gemm3<32, 64, 256>(X, W, B, g_h_user, NUSER, blockIdx.x * 256);
}

// folded attention vectors; also zeroes g_smax for both layers.
__global__ void u_k(const float* __restrict__ Ws, const float* __restrict__ Wd,
                    const float* __restrict__ as_, const float* __restrict__ ad_) {
    int id = blockIdx.x * 256 + threadIdx.x;
    if (blockIdx.x == 0 && threadIdx.x < 24) g_smax[threadIdx.x] = 0u;
    if (id >= 3072) return;
    int k = id & 63, h = (id >> 6) & 1, side = (id >> 7) & 1, rl = id >> 8;
    const float* a = (side ? ad_ : as_) + (size_t)rl * 128 + h * 64;
    const float* W = (side ? Wd : Ws) + (size_t)rl * 8192 + (size_t)h * 64 * 64;
    float u = 0.0f;
#pragma unroll 8
    for (int c = 0; c < 64; c++) u = fmaf(a[c], W[c * 64 + k], u);
    g_u[id] = u;
}

// ---------------- fused stage A: hs GEMMs | al scalars | reset ----------------
__global__ void __launch_bounds__(256) stage_a_k(const float* __restrict__ Wsrc,
                                                 const float* __restrict__ gb,
                                                 int l, int nhs, int nalb) {
    int b = blockIdx.x;
    if (b < nhs) {
        int idx = 0;
#pragma unroll
        for (int r = 1; r < 5; r++) if (b >= c_HSBLK2[l][r]) idx = r;
        int rel = c_HSREL2[l][idx];
        gemm3<64, 128, 128>(src_x(rel), Wsrc + ((size_t)l * 6 + rel) * 8192, nullptr,
                            g_hs + c_HSOFF[rel], c_NSRC[rel],
                            (b - c_HSBLK2[l][idx]) * 128);
        return;
    }
    if (b < nhs + nalb) {
        __shared__ unsigned int s_max[12];
        if (threadIdx.x < 12) s_max[threadIdx.x] = 0u;
        __syncthreads();
        int gid = (b - nhs) * 256 + threadIdx.x;
        if (gid < c_ALN[l]) {
            int t = 0;
#pragma unroll
            for (int i = 1; i < 10; i++) if (gid >= c_ALPFX2[l][i]) t = i;
            int n = gid - c_ALPFX2[l][t];
            int rel = c_ALREL2[l][t];
            int side = c_ALSIDE2[l][t];
            const float* xr = (side ? dst_x(rel) : src_x(rel)) + (size_t)n * 64;
            const float4* x4 = reinterpret_cast<const float4*>(xr);
            const float4* u4 = reinterpret_cast<const float4*>(
                g_u + ((size_t)(l * 6 + rel) * 2 + side) * 128);
            float a0 = 0.0f, a1 = 0.0f;
#pragma unroll
            for (int k = 0; k < 16; k++) {
                float4 xv = x4[k], u0 = u4[k], u1 = u4[16 + k];
                a0 = fmaf(xv.x, u0.x, fmaf(xv.y, u0.y, fmaf(xv.z, u0.z, fmaf(xv.w, u0.w, a0))));
                a1 = fmaf(xv.x, u1.x, fmaf(xv.y, u1.y, fmaf(xv.z, u1.z, fmaf(xv.w, u1.w, a1))));
            }
            float2 r; r.x = a0; r.y = a1;
            if (side) {
                g_al_d[c_DOFF[rel] + n] = r;
            } else {
                g_al_s[c_SOFF[rel] + n] = r;
                atomicMax(&s_max[rel * 2 + 0], encf(a0));
                atomicMax(&s_max[rel * 2 + 1], encf(a1));
            }
        }
        __syncthreads();
        if (threadIdx.x < 12 && s_max[threadIdx.x] != 0u)
            atomicMax(&g_smax[l * 12 + threadIdx.x], s_max[threadIdx.x]);
        return;
    }
    int gid = (b - nhs - nalb) * 256 + threadIdx.x;
    if (gid >= c_ACCN[l]) return;
    if (gid < NDST_TOT * 2) g_ss[gid] = 0.0f;
    int c = gid & 63;
    const float* bb = gb + l * 384;
    if (gid < NPOST * 64)
        g_acc_post[gid] = bb[0 * 64 + c] + bb[1 * 64 + c] + bb[5 * 64 + c];
    else
        g_acc_user[gid - NPOST * 64] = bb[3 * 64 + c] + bb[4 * 64 + c];
}

// stable-softmax numerators using the per-relation src-max upper bound
__global__ void __launch_bounds__(256) edge_sum_k(EdgeParams p, int l) {
    int gid = blockIdx.x * 256 + threadIdx.x;
    if (gid >= c_EN[l]) return;
    int idx = 0;
#pragma unroll
    for (int r = 1; r < 5; r++) if (gid >= c_EPFX2[l][r]) idx = r;
    int rel = c_EREL2[l][idx];
    int e = gid - c_EPFX2[l][idx];
    int s = p.src[rel][e], d = p.dst[rel][e];
    float2 as = g_al_s[c_SOFF[rel] + s];
    float2 ad = g_al_d[c_DOFF[rel] + d];
    float sm0 = decf(g_smax[l * 12 + rel * 2 + 0]);
    float sm1 = decf(g_smax[l * 12 + rel * 2 + 1]);
    float e0 = lrelu(as.x + ad.x);
    float e1 = lrelu(as.y + ad.y);
    float m0 = lrelu(sm0 + ad.x);
    float m1 = lrelu(sm1 + ad.y);
    int di = (c_DOFF[rel] + d) * 2;
    float p0 = __expf(e0 - m0);
    float p1 = __expf(e1 - m1);
    atomicAdd(&g_ss[di + 0], p0);
    atomicAdd(&g_ss[di + 1], p1);
    float2 pr; pr.x = p0; pr.y = p1;
    g_p[gid] = pr;
}

// invert ALL denominators in place (ss is indexed by (DOFF+d)*2 — rel 5 lives
// at [640000,840000); do NOT truncate this range), folding head-mean 0.5x
__global__ void inv_k() {
    int gid = blockIdx.x * 256 + threadIdx.x;
    if (gid >= NDST_TOT * 2) return;
    g_ss[gid] = 0.5f / (g_ss[gid] + 1e-16f);
}

// 16 threads per edge, 4 channels each; single float4 vector atomic per thread
__global__ void __launch_bounds__(256) edge_msg_k(EdgeParams p, int l) {
    int gid = blockIdx.x * 256 + threadIdx.x;
    int e = gid >> 4, c0 = (gid & 15) << 2;
    if (e >= c_EN[l]) return;
    int idx = 0;
#pragma unroll
    for (int r = 1; r < 5; r++) if (e >= c_EPFX2[l][r]) idx = r;
    int rel = c_EREL2[l][idx];
    int eloc = e - c_EPFX2[l][idx];
    int s = p.src[rel][eloc], d = p.dst[rel][eloc];
    float2 pr = g_p[e];
    int di = (c_DOFF[rel] + d) * 2;
    float a0 = pr.x * g_ss[di + 0];
    float a1 = pr.y * g_ss[di + 1];
    const float* hsrow = g_hs + c_HSOFF[rel] + (size_t)s * 128;
    float4 h0 = *reinterpret_cast<const float4*>(hsrow + c0);
    float4 h1 = *reinterpret_cast<const float4*>(hsrow + 64 + c0);
    float4 v;
    v.x = a0 * h0.x + a1 * h1.x;
    v.y = a0 * h0.y + a1 * h1.y;
    v.z = a0 * h0.z + a1 * h1.z;
    v.w = a0 * h0.w + a1 * h1.w;
    float4* acc = reinterpret_cast<float4*>(out_acc(rel) + (size_t)d * 64 + c0);
    atomicAdd(acc, v);
}

// layer-0 relu: post + user only
__global__ void relu_k() {
    int gid = blockIdx.x * 256 + threadIdx.x;
    if (gid >= 9600000) return;
    if (gid < NPOST * 64)
        g_h_post[gid] = fmaxf(g_acc_post[gid], 0.0f);
    else {
        int i = gid - NPOST * 64;
        g_h_user[i] = fmaxf(g_acc_user[i], 0.0f);
    }
}

// classifier: one warp per post node; layer-2 relu folded into the load
__global__ void __launch_bounds__(256) cls_k(const float* __restrict__ w1,
                                             const float* __restrict__ b1,
                                             const float* __restrict__ w2,
                                             const float* __restrict__ b2,
                                             float* __restrict__ out) {
    int gid = blockIdx.x * 256 + threadIdx.x;
    int n = gid >> 5, lane = gid & 31;
    if (n >= NPOST) return;
    const float4* x4 = reinterpret_cast<const float4*>(g_acc_post + (size_t)n * 64);
    const float4* w4 = reinterpret_cast<const float4*>(w1 + (size_t)lane * 64);
    float a = 0.0f;
#pragma unroll
    for (int k = 0; k < 16; k++) {
        float4 xv = x4[k], wv = w4[k];
        xv.x = fmaxf(xv.x, 0.0f); xv.y = fmaxf(xv.y, 0.0f);
        xv.z = fmaxf(xv.z, 0.0f); xv.w = fmaxf(xv.w, 0.0f);
        a = fmaf(xv.x, wv.x, fmaf(xv.y, wv.y, fmaf(xv.z, wv.z, fmaf(xv.w, wv.w, a))));
    }
    float h = fmaxf(a + b1[lane], 0.0f) * w2[lane];
#pragma unroll
    for (int off = 16; off > 0; off >>= 1)
        h += __shfl_xor_sync(0xffffffffu, h, off);
    if (lane == 0) out[n] = h + b2[0];
}

// ---------------- launch ----------------
extern "C" void kernel_launch(void* const* d_in, const int* in_sizes, int n_in,
                              void* d_out, int out_size) {
    const float* x_post = (const float*)d_in[0];
    const float* x_user = (const float*)d_in[1];
    EdgeParams ep;
    for (int r = 0; r < 6; r++) {
        ep.src[r] = (const int*)d_in[3 + 2 * r];
        ep.dst[r] = (const int*)d_in[4 + 2 * r];
    }
    const float* post_w = (const float*)d_in[15];
    const float* post_b = (const float*)d_in[16];
    const float* user_w = (const float*)d_in[17];
    const float* user_b = (const float*)d_in[18];
    const float* W_src  = (const float*)d_in[21];
    const float* W_dst  = (const float*)d_in[22];
    const float* a_src  = (const float*)d_in[23];
    const float* a_dst  = (const float*)d_in[24];
    const float* gat_b  = (const float*)d_in[25];
    const float* cls_w1 = (const float*)d_in[26];
    const float* cls_b1 = (const float*)d_in[27];
    const float* cls_w2 = (const float*)d_in[28];
    const float* cls_b2 = (const float*)d_in[29];
    float* out = (float*)d_out;

    proj_post_k<<<391, 256>>>(x_post, post_w, post_b);
    proj_user_k<<<196, 256>>>(x_user, user_w, user_b);
    u_k<<<12, 256>>>(W_src, W_dst, a_src, a_dst);

    // layer 0: rels {0,1,3,4,5}; hs blocks of 128 rows -> 391*4 + 782 = 2346
    stage_a_k<<<2346 + 2735 + 37500, 256>>>(W_src, gat_b, 0, 2346, 2735);
    edge_sum_k<<<5274, 256>>>(ep, 0);
    inv_k<<<3282, 256>>>();
    edge_msg_k<<<84375, 256>>>(ep, 0);
    relu_k<<<37500, 256>>>();

    // layer 1: rels {0,1,5}; hs blocks 391+391+782 = 1564
    stage_a_k<<<1564 + 1954 + 25000, 256>>>(W_src, gat_b, 1, 1564, 1954);
    edge_sum_k<<<2149, 256>>>(ep, 1);
    inv_k<<<3282, 256>>>();
    edge_msg_k<<<34375, 256>>>(ep, 1);

    cls_k<<<12500, 256>>>(cls_w1, cls_b1, cls_w2, cls_b2, out);
}

// round 15
// speedup vs baseline: 2.4351x; 1.0208x over previous
#include <cuda_runtime.h>
#include <cuda_bf16.h>
#include <cuda_fp16.h>
#include <cstdint>

#define NPOST 100000
#define NUSER 50000
#define NSRC_TOT 400000
#define NDST_TOT 420000
#define BIG (1 << 29)

// ---------------- static device scratch ----------------
__device__ float g_h_post[NPOST * 64];
__device__ float g_h_user[NUSER * 64];
__device__ float g_acc_post[NPOST * 64];
__device__ float g_acc_user[NUSER * 64];
__device__ __half g_hs[51200000];       // concat per-relation hs [N_src][128], fp16
__device__ float2 g_al_s[NSRC_TOT];
__device__ float2 g_al_d[NDST_TOT];
__device__ float        g_ss[NDST_TOT * 2]; // softmax denom -> inverted in place
__device__ float2 g_p[1350000];             // unnormalized softmax numerators
__device__ float g_u[3072];             // folded attention vectors [l][r][side][h][64]
__device__ unsigned int g_smax[24];     // encoded per-(layer,rel,head) max of al_s

// ---------------- constant tables ----------------
__constant__ int c_SOFF[6]  = {0, 50000, 100000, 200000, 250000, 300000};
__constant__ int c_DOFF[6]  = {0, 100000, 200000, 220000, 270000, 320000};
__constant__ int c_HSOFF[6] = {0, 6400000, 12800000, 25600000, 32000000, 38400000};
__constant__ int c_NSRC[6]  = {50000, 50000, 100000, 50000, 50000, 100000};

// per-layer live-relation dispatch (ent + rel2 dead; layer1 post rels only)
// hs blocks of 128 nodes: NSRC 50k -> 391 blocks, 100k -> 782 blocks
__constant__ int c_HSBLK2[2][5] = {{0, 391, 782, 1173, 1564},
                                   {0, 391, 782, BIG, BIG}};
__constant__ int c_HSREL2[2][5] = {{0, 1, 3, 4, 5}, {0, 1, 5, 5, 5}};
__constant__ int c_ALPFX2[2][10] = {
    {0, 50000, 100000, 150000, 200000, 300000, 400000, 500000, 550000, 600000},
    {0, 50000, 100000, 200000, 300000, 400000, BIG, BIG, BIG, BIG}};
__constant__ int c_ALREL2[2][10] = {{0, 1, 3, 4, 5, 0, 1, 3, 4, 5},
                                    {0, 1, 5, 0, 1, 5, 5, 5, 5, 5}};
__constant__ int c_ALSIDE2[2][10] = {{0, 0, 0, 0, 0, 1, 1, 1, 1, 1},
                                     {0, 0, 0, 1, 1, 1, 1, 1, 1, 1}};
__constant__ int c_ALN[2] = {700000, 500000};
__constant__ int c_EPFX2[2][5] = {{0, 100000, 300000, 700000, 1100000},
                                  {0, 100000, 300000, BIG, BIG}};
__constant__ int c_EREL2[2][5] = {{0, 1, 3, 4, 5}, {0, 1, 5, 5, 5}};
__constant__ int c_EN[2] = {1350000, 550000};
__constant__ int c_ACCN[2] = {9600000, 6400000};

struct EdgeParams { const int* src[6]; const int* dst[6]; };

// ---------------- helpers ----------------
__device__ __forceinline__ const float* src_x(int rel) {
    return (rel == 5) ? g_h_post : g_h_user;
}
__device__ __forceinline__ const float* dst_x(int rel) {
    return (rel == 3 || rel == 4) ? g_h_user : g_h_post;
}
__device__ __forceinline__ float* out_acc(int rel) {
    return (rel == 3 || rel == 4) ? g_acc_user : g_acc_post;
}
__device__ __forceinline__ float lrelu(float x) { return x > 0.0f ? x : 0.2f * x; }
__device__ __forceinline__ unsigned int encf(float f) {
    unsigned int u = __float_as_uint(f);
    return (u & 0x80000000u) ? ~u : (u | 0x80000000u);
}
__device__ __forceinline__ float decf(unsigned int u) {
    return (u & 0x80000000u) ? __uint_as_float(u & 0x7fffffffu) : __uint_as_float(~u);
}
__device__ __forceinline__ unsigned int h2bits(__half2 h) {
    return *reinterpret_cast<unsigned int*>(&h);
}

// ---------------- 8x8-tile GEMM: Y[n][m] = sum_k X[n][k]*W[m][k] (+ B[m]) ----------------
// 256 threads, ROWS x M block tile (ROWS*M = 16384), KT=32.
// Per-thread 8 rows x 8 cols split as {cg*4..+3, cg*4+M/2..+3} (conflict-free).
// OT = float (proj) or __half (hs); accumulation always fp32.
template <int K, int M, int ROWS, typename OT>
__device__ __forceinline__ void gemm3(const float* __restrict__ X,
                                      const float* __restrict__ W,
                                      const float* __restrict__ B,
                                      OT* __restrict__ Y, int N, int n0)
{
    constexpr int XR = ROWS + 4;
    constexpr int WR = M + 4;
    constexpr int CG = M / 8;                     // col groups (8 or 16)
    constexpr int CH = M / 2;                     // column-half offset
    constexpr int XNF = (ROWS == 256) ? 32 : 16;  // X floats staged per thread
    constexpr int WNF = (M == 64) ? 8 : 16;       // W floats staged per thread
    __shared__ float Xs[32 * XR];
    __shared__ float Ws[32 * WR];

    const int t = threadIdx.x;
    const int cg = t % CG, rg = t / CG;
    const int col0 = cg * 4;
    const int row0 = rg * 8;

    const int xn  = (ROWS == 256) ? t : (t & 127);
    const int xk0 = (ROWS == 256) ? 0 : ((t >> 7) * 16);
    const int wm  = (M == 64) ? (t & 63) : (t & 127);
    const int wk0 = (M == 64) ? ((t >> 6) * 8) : ((t >> 7) * 16);

    float acc[8][8];
#pragma unroll
    for (int i = 0; i < 8; i++)
#pragma unroll
        for (int j = 0; j < 8; j++) acc[i][j] = 0.0f;

    const bool xok = (n0 + xn) < N;

    for (int k0 = 0; k0 < K; k0 += 32) {
        float4 xr[XNF / 4];
#pragma unroll
        for (int j = 0; j < XNF / 4; j++) xr[j] = make_float4(0.f, 0.f, 0.f, 0.f);
        if (xok) {
            const float4* g = reinterpret_cast<const float4*>(
                X + (size_t)(n0 + xn) * K + k0 + xk0);
#pragma unroll
            for (int j = 0; j < XNF / 4; j++) xr[j] = g[j];
        }
        float4 wr[WNF / 4];
        {
            const float4* g = reinterpret_cast<const float4*>(
                W + (size_t)wm * K + k0 + wk0);
#pragma unroll
            for (int j = 0; j < WNF / 4; j++) wr[j] = g[j];
        }
        __syncthreads();   // previous tile fully consumed
#pragma unroll
        for (int j = 0; j < XNF / 4; j++) {
            Xs[(xk0 + 4 * j + 0) * XR + xn] = xr[j].x;
            Xs[(xk0 + 4 * j + 1) * XR + xn] = xr[j].y;
            Xs[(xk0 + 4 * j + 2) * XR + xn] = xr[j].z;
            Xs[(xk0 + 4 * j + 3) * XR + xn] = xr[j].w;
        }
#pragma unroll
        for (int j = 0; j < WNF / 4; j++) {
            Ws[(wk0 + 4 * j + 0) * WR + wm] = wr[j].x;
            Ws[(wk0 + 4 * j + 1) * WR + wm] = wr[j].y;
            Ws[(wk0 + 4 * j + 2) * WR + wm] = wr[j].z;
            Ws[(wk0 + 4 * j + 3) * WR + wm] = wr[j].w;
        }
        __syncthreads();

#pragma unroll
        for (int kk = 0; kk < 32; kk++) {
            float4 xa = *reinterpret_cast<const float4*>(&Xs[kk * XR + row0]);
            float4 xb = *reinterpret_cast<const float4*>(&Xs[kk * XR + row0 + 4]);
            float4 wa = *reinterpret_cast<const float4*>(&Ws[kk * WR + col0]);
            float4 wb = *reinterpret_cast<const float4*>(&Ws[kk * WR + col0 + CH]);
            float xv[8] = {xa.x, xa.y, xa.z, xa.w, xb.x, xb.y, xb.z, xb.w};
            float wv[8] = {wa.x, wa.y, wa.z, wa.w, wb.x, wb.y, wb.z, wb.w};
#pragma unroll
            for (int i = 0; i < 8; i++)
#pragma unroll
                for (int j = 0; j < 8; j++)
                    acc[i][j] = fmaf(xv[i], wv[j], acc[i][j]);
        }
        __syncthreads();
    }

    float bj[8];
#pragma unroll
    for (int j = 0; j < 4; j++) {
        bj[j]     = B ? B[col0 + j]      : 0.0f;
        bj[4 + j] = B ? B[col0 + CH + j] : 0.0f;
    }
#pragma unroll
    for (int i = 0; i < 8; i++) {
        int n = n0 + row0 + i;
        if (n < N) {
            if (sizeof(OT) == 2) {
                // fp16 output: two 8B stores (4 halves each)
                __half* Yh = reinterpret_cast<__half*>(Y);
                uint2 v0, v1;
                v0.x = h2bits(__floats2half2_rn(acc[i][0] + bj[0], acc[i][1] + bj[1]));
                v0.y = h2bits(__floats2half2_rn(acc[i][2] + bj[2], acc[i][3] + bj[3]));
                v1.x = h2bits(__floats2half2_rn(acc[i][4] + bj[4], acc[i][5] + bj[5]));
                v1.y = h2bits(__floats2half2_rn(acc[i][6] + bj[6], acc[i][7] + bj[7]));
                *reinterpret_cast<uint2*>(Yh + (size_t)n * M + col0)      = v0;
                *reinterpret_cast<uint2*>(Yh + (size_t)n * M + col0 + CH) = v1;
            } else {
                float* Yf = reinterpret_cast<float*>(Y);
                float4 v0, v1;
                v0.x = acc[i][0] + bj[0]; v0.y = acc[i][1] + bj[1];
                v0.z = acc[i][2] + bj[2]; v0.w = acc[i][3] + bj[3];
                v1.x = acc[i][4] + bj[4]; v1.y = acc[i][5] + bj[5];
                v1.z = acc[i][6] + bj[6]; v1.w = acc[i][7] + bj[7];
                *reinterpret_cast<float4*>(Yf + (size_t)n * M + col0)      = v0;
                *reinterpret_cast<float4*>(Yf + (size_t)n * M + col0 + CH) = v1;
            }
        }
    }
}

// ---------------- standalone projection kernels ----------------
__global__ void __launch_bounds__(256) proj_post_k(const float* X, const float* W, const float* B) {
    gemm3<768, 64, 256, float>(X, W, B, g_h_post, NPOST, blockIdx.x * 256);
}
__global__ void __launch_bounds__(256) proj_user_k(const float* X, const float* W, const float* B) {
    gemm3<32, 64, 256, float>(X, W, B, g_h_user, NUSER, blockIdx.x * 256);
}

// folded attention vectors; also zeroes g_smax for both layers.
__global__ void u_k(const float* __restrict__ Ws, const float* __restrict__ Wd,
                    const float* __restrict__ as_, const float* __restrict__ ad_) {
    int id = blockIdx.x * 256 + threadIdx.x;
    if (blockIdx.x == 0 && threadIdx.x < 24) g_smax[threadIdx.x] = 0u;
    if (id >= 3072) return;
    int k = id & 63, h = (id >> 6) & 1, side = (id >> 7) & 1, rl = id >> 8;
    const float* a = (side ? ad_ : as_) + (size_t)rl * 128 + h * 64;
    const float* W = (side ? Wd : Ws) + (size_t)rl * 8192 + (size_t)h * 64 * 64;
    float u = 0.0f;
#pragma unroll 8
    for (int c = 0; c < 64; c++) u = fmaf(a[c], W[c * 64 + k], u);
    g_u[id] = u;
}

// ---------------- fused stage A: hs GEMMs | al scalars | reset ----------------
__global__ void __launch_bounds__(256) stage_a_k(const float* __restrict__ Wsrc,
                                                 const float* __restrict__ gb,
                                                 int l, int nhs, int nalb) {
    int b = blockIdx.x;
    if (b < nhs) {
        int idx = 0;
#pragma unroll
        for (int r = 1; r < 5; r++) if (b >= c_HSBLK2[l][r]) idx = r;
        int rel = c_HSREL2[l][idx];
        gemm3<64, 128, 128, __half>(src_x(rel), Wsrc + ((size_t)l * 6 + rel) * 8192,
                                    nullptr, g_hs + c_HSOFF[rel], c_NSRC[rel],
                                    (b - c_HSBLK2[l][idx]) * 128);
        return;
    }
    if (b < nhs + nalb) {
        __shared__ unsigned int s_max[12];
        if (threadIdx.x < 12) s_max[threadIdx.x] = 0u;
        __syncthreads();
        int gid = (b - nhs) * 256 + threadIdx.x;
        if (gid < c_ALN[l]) {
            int t = 0;
#pragma unroll
            for (int i = 1; i < 10; i++) if (gid >= c_ALPFX2[l][i]) t = i;
            int n = gid - c_ALPFX2[l][t];
            int rel = c_ALREL2[l][t];
            int side = c_ALSIDE2[l][t];
            const float* xr = (side ? dst_x(rel) : src_x(rel)) + (size_t)n * 64;
            const float4* x4 = reinterpret_cast<const float4*>(xr);
            const float4* u4 = reinterpret_cast<const float4*>(
                g_u + ((size_t)(l * 6 + rel) * 2 + side) * 128);
            float a0 = 0.0f, a1 = 0.0f;
#pragma unroll
            for (int k = 0; k < 16; k++) {
                float4 xv = x4[k], u0 = u4[k], u1 = u4[16 + k];
                a0 = fmaf(xv.x, u0.x, fmaf(xv.y, u0.y, fmaf(xv.z, u0.z, fmaf(xv.w, u0.w, a0))));
                a1 = fmaf(xv.x, u1.x, fmaf(xv.y, u1.y, fmaf(xv.z, u1.z, fmaf(xv.w, u1.w, a1))));
            }
            float2 r; r.x = a0; r.y = a1;
            if (side) {
                g_al_d[c_DOFF[rel] + n] = r;
            } else {
                g_al_s[c_SOFF[rel] + n] = r;
                atomicMax(&s_max[rel * 2 + 0], encf(a0));
                atomicMax(&s_max[rel * 2 + 1], encf(a1));
            }
        }
        __syncthreads();
        if (threadIdx.x < 12 && s_max[threadIdx.x] != 0u)
            atomicMax(&g_smax[l * 12 + threadIdx.x], s_max[threadIdx.x]);
        return;
    }
    int gid = (b - nhs - nalb) * 256 + threadIdx.x;
    if (gid >= c_ACCN[l]) return;
    if (gid < NDST_TOT * 2) g_ss[gid] = 0.0f;
    int c = gid & 63;
    const float* bb = gb + l * 384;
    if (gid < NPOST * 64)
        g_acc_post[gid] = bb[0 * 64 + c] + bb[1 * 64 + c] + bb[5 * 64 + c];
    else
        g_acc_user[gid - NPOST * 64] = bb[3 * 64 + c] + bb[4 * 64 + c];
}

// stable-softmax numerators using the per-relation src-max upper bound
__global__ void __launch_bounds__(256) edge_sum_k(EdgeParams p, int l) {
    int gid = blockIdx.x * 256 + threadIdx.x;
    if (gid >= c_EN[l]) return;
    int idx = 0;
#pragma unroll
    for (int r = 1; r < 5; r++) if (gid >= c_EPFX2[l][r]) idx = r;
    int rel = c_EREL2[l][idx];
    int e = gid - c_EPFX2[l][idx];
    int s = p.src[rel][e], d = p.dst[rel][e];
    float2 as = g_al_s[c_SOFF[rel] + s];
    float2 ad = g_al_d[c_DOFF[rel] + d];
    float sm0 = decf(g_smax[l * 12 + rel * 2 + 0]);
    float sm1 = decf(g_smax[l * 12 + rel * 2 + 1]);
    float e0 = lrelu(as.x + ad.x);
    float e1 = lrelu(as.y + ad.y);
    float m0 = lrelu(sm0 + ad.x);
    float m1 = lrelu(sm1 + ad.y);
    int di = (c_DOFF[rel] + d) * 2;
    float p0 = __expf(e0 - m0);
    float p1 = __expf(e1 - m1);
    atomicAdd(&g_ss[di + 0], p0);
    atomicAdd(&g_ss[di + 1], p1);
    float2 pr; pr.x = p0; pr.y = p1;
    g_p[gid] = pr;
}

// invert ALL denominators in place (ss indexed by (DOFF+d)*2 — rel 5 lives at
// [640000,840000); do NOT truncate), folding head-mean 0.5x
__global__ void inv_k() {
    int gid = blockIdx.x * 256 + threadIdx.x;
    if (gid >= NDST_TOT * 2) return;
    g_ss[gid] = 0.5f / (g_ss[gid] + 1e-16f);
}

// 16 threads per edge, 4 channels each; fp16 hs gather, fp32 math,
// single float4 vector atomic per thread
__global__ void __launch_bounds__(256) edge_msg_k(EdgeParams p, int l) {
    int gid = blockIdx.x * 256 + threadIdx.x;
    int e = gid >> 4, c0 = (gid & 15) << 2;
    if (e >= c_EN[l]) return;
    int idx = 0;
#pragma unroll
    for (int r = 1; r < 5; r++) if (e >= c_EPFX2[l][r]) idx = r;
    int rel = c_EREL2[l][idx];
    int eloc = e - c_EPFX2[l][idx];
    int s = p.src[rel][eloc], d = p.dst[rel][eloc];
    float2 pr = g_p[e];
    int di = (c_DOFF[rel] + d) * 2;
    float a0 = pr.x * g_ss[di + 0];
    float a1 = pr.y * g_ss[di + 1];
    const __half* hsrow = g_hs + c_HSOFF[rel] + (size_t)s * 128;
    uint2 r0 = *reinterpret_cast<const uint2*>(hsrow + c0);
    uint2 r1 = *reinterpret_cast<const uint2*>(hsrow + 64 + c0);
    float2 f00 = __half22float2(*reinterpret_cast<__half2*>(&r0.x));
    float2 f01 = __half22float2(*reinterpret_cast<__half2*>(&r0.y));
    float2 f10 = __half22float2(*reinterpret_cast<__half2*>(&r1.x));
    float2 f11 = __half22float2(*reinterpret_cast<__half2*>(&r1.y));
    float4 v;
    v.x = a0 * f00.x + a1 * f10.x;
    v.y = a0 * f00.y + a1 * f10.y;
    v.z = a0 * f01.x + a1 * f11.x;
    v.w = a0 * f01.y + a1 * f11.y;
    float4* acc = reinterpret_cast<float4*>(out_acc(rel) + (size_t)d * 64 + c0);
    atomicAdd(acc, v);
}

// layer-0 relu: post + user only
__global__ void relu_k() {
    int gid = blockIdx.x * 256 + threadIdx.x;
    if (gid >= 9600000) return;
    if (gid < NPOST * 64)
        g_h_post[gid] = fmaxf(g_acc_post[gid], 0.0f);
    else {
        int i = gid - NPOST * 64;
        g_h_user[i] = fmaxf(g_acc_user[i], 0.0f);
    }
}

// classifier: one warp per post node; layer-2 relu folded into the load
__global__ void __launch_bounds__(256) cls_k(const float* __restrict__ w1,
                                             const float* __restrict__ b1,
                                             const float* __restrict__ w2,
                                             const float* __restrict__ b2,
                                             float* __restrict__ out) {
    int gid = blockIdx.x * 256 + threadIdx.x;
    int n = gid >> 5, lane = gid & 31;
    if (n >= NPOST) return;
    const float4* x4 = reinterpret_cast<const float4*>(g_acc_post + (size_t)n * 64);
    const float4* w4 = reinterpret_cast<const float4*>(w1 + (size_t)lane * 64);
    float a = 0.0f;
#pragma unroll
    for (int k = 0; k < 16; k++) {
        float4 xv = x4[k], wv = w4[k];
        xv.x = fmaxf(xv.x, 0.0f); xv.y = fmaxf(xv.y, 0.0f);
        xv.z = fmaxf(xv.z, 0.0f); xv.w = fmaxf(xv.w, 0.0f);
        a = fmaf(xv.x, wv.x, fmaf(xv.y, wv.y, fmaf(xv.z, wv.z, fmaf(xv.w, wv.w, a))));
    }
    float h = fmaxf(a + b1[lane], 0.0f) * w2[lane];
#pragma unroll
    for (int off = 16; off > 0; off >>= 1)
        h += __shfl_xor_sync(0xffffffffu, h, off);
    if (lane == 0) out[n] = h + b2[0];
}

// ---------------- launch ----------------
extern "C" void kernel_launch(void* const* d_in, const int* in_sizes, int n_in,
                              void* d_out, int out_size) {
    const float* x_post = (const float*)d_in[0];
    const float* x_user = (const float*)d_in[1];
    EdgeParams ep;
    for (int r = 0; r < 6; r++) {
        ep.src[r] = (const int*)d_in[3 + 2 * r];
        ep.dst[r] = (const int*)d_in[4 + 2 * r];
    }
    const float* post_w = (const float*)d_in[15];
    const float* post_b = (const float*)d_in[16];
    const float* user_w = (const float*)d_in[17];
    const float* user_b = (const float*)d_in[18];
    const float* W_src  = (const float*)d_in[21];
    const float* W_dst  = (const float*)d_in[22];
    const float* a_src  = (const float*)d_in[23];
    const float* a_dst  = (const float*)d_in[24];
    const float* gat_b  = (const float*)d_in[25];
    const float* cls_w1 = (const float*)d_in[26];
    const float* cls_b1 = (const float*)d_in[27];
    const float* cls_w2 = (const float*)d_in[28];
    const float* cls_b2 = (const float*)d_in[29];
    float* out = (float*)d_out;

    proj_post_k<<<391, 256>>>(x_post, post_w, post_b);
    proj_user_k<<<196, 256>>>(x_user, user_w, user_b);
    u_k<<<12, 256>>>(W_src, W_dst, a_src, a_dst);

    // layer 0: rels {0,1,3,4,5}
    stage_a_k<<<2346 + 2735 + 37500, 256>>>(W_src, gat_b, 0, 2346, 2735);
    edge_sum_k<<<5274, 256>>>(ep, 0);
    inv_k<<<3282, 256>>>();
    edge_msg_k<<<84375, 256>>>(ep, 0);
    relu_k<<<37500, 256>>>();

    // layer 1: rels {0,1,5}
    stage_a_k<<<1564 + 1954 + 25000, 256>>>(W_src, gat_b, 1, 1564, 1954);
    edge_sum_k<<<2149, 256>>>(ep, 1);
    inv_k<<<3282, 256>>>();
    edge_msg_k<<<34375, 256>>>(ep, 1);

    cls_k<<<12500, 256>>>(cls_w1, cls_b1, cls_w2, cls_b2, out);
}

// round 16
// speedup vs baseline: 3.0539x; 1.2542x over previous
#include <cuda_runtime.h>
#include <cuda_bf16.h>
#include <cuda_fp16.h>
#include <cstdint>

#define NPOST 100000
#define NUSER 50000
#define NSRC_TOT 400000
#define NDST_TOT 420000
#define NEDGE_LIVE 1350000
#define BIG (1 << 29)

// ---------------- static device scratch ----------------
__device__ float g_h_post[NPOST * 64];
__device__ float g_h_user[NUSER * 64];
__device__ float g_acc_post[NPOST * 64];
__device__ __half g_hs[51200000];       // concat per-relation hs [N_src][128], fp16
__device__ float2 g_al_s[NSRC_TOT];
__device__ float2 g_al_d[NDST_TOT];
__device__ float g_u[3072];             // folded attention vectors [l][r][side][h][64]
__device__ unsigned int g_smax[24];     // encoded per-(layer,rel,head) max of al_s
// CSR (built once per launch; graph is static)
__device__ int g_cnt[NDST_TOT];
__device__ int g_off[NDST_TOT];
__device__ int g_fill[NDST_TOT];
__device__ int g_bsum[128];
__device__ int g_csr_src[NEDGE_LIVE];

// ---------------- constant tables ----------------
__constant__ int c_SOFF[6]  = {0, 50000, 100000, 200000, 250000, 300000};
__constant__ int c_DOFF[6]  = {0, 100000, 200000, 220000, 270000, 320000};
__constant__ int c_HSOFF[6] = {0, 6400000, 12800000, 25600000, 32000000, 38400000};
__constant__ int c_NSRC[6]  = {50000, 50000, 100000, 50000, 50000, 100000};

// per-layer live-relation dispatch (ent + rel2 dead; layer1 post rels only)
__constant__ int c_HSBLK2[2][5] = {{0, 391, 782, 1173, 1564},
                                   {0, 391, 782, BIG, BIG}};
__constant__ int c_HSREL2[2][5] = {{0, 1, 3, 4, 5}, {0, 1, 5, 5, 5}};
__constant__ int c_ALPFX2[2][10] = {
    {0, 50000, 100000, 150000, 200000, 300000, 400000, 500000, 550000, 600000},
    {0, 50000, 100000, 200000, 300000, 400000, BIG, BIG, BIG, BIG}};
__constant__ int c_ALREL2[2][10] = {{0, 1, 3, 4, 5, 0, 1, 3, 4, 5},
                                    {0, 1, 5, 0, 1, 5, 5, 5, 5, 5}};
__constant__ int c_ALSIDE2[2][10] = {{0, 0, 0, 0, 0, 1, 1, 1, 1, 1},
                                     {0, 0, 0, 1, 1, 1, 1, 1, 1, 1}};
__constant__ int c_ALN[2] = {700000, 500000};
// live-edge dispatch (L0 set == all live edges, used for CSR build too)
__constant__ int c_EPFX[5] = {0, 100000, 300000, 700000, 1100000};
__constant__ int c_EREL[5] = {0, 1, 3, 4, 5};
__constant__ int c_PREL[3] = {0, 1, 5};   // post-dst relations
__constant__ int c_UREL[2] = {3, 4};      // user-dst relations

struct EdgeParams { const int* src[6]; const int* dst[6]; };

// ---------------- helpers ----------------
__device__ __forceinline__ const float* src_x(int rel) {
    return (rel == 5) ? g_h_post : g_h_user;
}
__device__ __forceinline__ const float* dst_x(int rel) {
    return (rel == 3 || rel == 4) ? g_h_user : g_h_post;
}
__device__ __forceinline__ float lrelu(float x) { return x > 0.0f ? x : 0.2f * x; }
__device__ __forceinline__ unsigned int encf(float f) {
    unsigned int u = __float_as_uint(f);
    return (u & 0x80000000u) ? ~u : (u | 0x80000000u);
}
__device__ __forceinline__ float decf(unsigned int u) {
    return (u & 0x80000000u) ? __uint_as_float(u & 0x7fffffffu) : __uint_as_float(~u);
}
__device__ __forceinline__ unsigned int h2bits(__half2 h) {
    return *reinterpret_cast<unsigned int*>(&h);
}

// ---------------- CSR build (once per launch) ----------------
__global__ void zero_cnt_k() {
    int i = blockIdx.x * 256 + threadIdx.x;
    if (i < NDST_TOT) g_cnt[i] = 0;
}
__global__ void hist_k(EdgeParams p) {
    int gid = blockIdx.x * 256 + threadIdx.x;
    if (gid >= NEDGE_LIVE) return;
    int idx = 0;
#pragma unroll
    for (int r = 1; r < 5; r++) if (gid >= c_EPFX[r]) idx = r;
    int rel = c_EREL[idx];
    int e = gid - c_EPFX[idx];
    atomicAdd(&g_cnt[c_DOFF[rel] + p.dst[rel][e]], 1);
}
// block-local exclusive scan: 512 threads x 8 elems = 4096/block
__global__ void scan1_k() {
    __shared__ int sm[512];
    int b = blockIdx.x, t = threadIdx.x;
    int base = b * 4096 + t * 8;
    int v[8], s = 0;
#pragma unroll
    for (int i = 0; i < 8; i++) {
        int idx = base + i;
        v[i] = (idx < NDST_TOT) ? g_cnt[idx] : 0;
        s += v[i];
    }
    sm[t] = s;
    __syncthreads();
    for (int o = 1; o < 512; o <<= 1) {
        int x = (t >= o) ? sm[t - o] : 0;
        __syncthreads();
        sm[t] += x;
        __syncthreads();
    }
    int run = sm[t] - s;   // exclusive base for this thread
    if (t == 511) g_bsum[b] = sm[511];
#pragma unroll
    for (int i = 0; i < 8; i++) {
        int idx = base + i;
        if (idx < NDST_TOT) g_off[idx] = run;
        run += v[i];
    }
}
__global__ void scan2_k(int nb) {
    if (threadIdx.x == 0 && blockIdx.x == 0) {
        int run = 0;
        for (int i = 0; i < nb; i++) { int t = g_bsum[i]; g_bsum[i] = run; run += t; }
    }
}
__global__ void scan3_k() {
    int i = blockIdx.x * 256 + threadIdx.x;
    if (i >= NDST_TOT) return;
    int o = g_off[i] + g_bsum[i >> 12];
    g_off[i] = o;
    g_fill[i] = o;
}
__global__ void scatter_k(EdgeParams p) {
    int gid = blockIdx.x * 256 + threadIdx.x;
    if (gid >= NEDGE_LIVE) return;
    int idx = 0;
#pragma unroll
    for (int r = 1; r < 5; r++) if (gid >= c_EPFX[r]) idx = r;
    int rel = c_EREL[idx];
    int e = gid - c_EPFX[idx];
    int pos = atomicAdd(&g_fill[c_DOFF[rel] + p.dst[rel][e]], 1);
    g_csr_src[pos] = p.src[rel][e];
}

// ---------------- 8x8-tile GEMM (proven; OT=float or __half, fp32 accum) ----------------
template <int K, int M, int ROWS, typename OT>
__device__ __forceinline__ void gemm3(const float* __restrict__ X,
                                      const float* __restrict__ W,
                                      const float* __restrict__ B,
                                      OT* __restrict__ Y, int N, int n0)
{
    constexpr int XR = ROWS + 4;
    constexpr int WR = M + 4;
    constexpr int CG = M / 8;
    constexpr int CH = M / 2;
    constexpr int XNF = (ROWS == 256) ? 32 : 16;
    constexpr int WNF = (M == 64) ? 8 : 16;
    __shared__ float Xs[32 * XR];
    __shared__ float Ws[32 * WR];

    const int t = threadIdx.x;
    const int cg = t % CG, rg = t / CG;
    const int col0 = cg * 4;
    const int row0 = rg * 8;

    const int xn  = (ROWS == 256) ? t : (t & 127);
    const int xk0 = (ROWS == 256) ? 0 : ((t >> 7) * 16);
    const int wm  = (M == 64) ? (t & 63) : (t & 127);
    const int wk0 = (M == 64) ? ((t >> 6) * 8) : ((t >> 7) * 16);

    float acc[8][8];
#pragma unroll
    for (int i = 0; i < 8; i++)
#pragma unroll
        for (int j = 0; j < 8; j++) acc[i][j] = 0.0f;

    const bool xok = (n0 + xn) < N;

    for (int k0 = 0; k0 < K; k0 += 32) {
        float4 xr[XNF / 4];
#pragma unroll
        for (int j = 0; j < XNF / 4; j++) xr[j] = make_float4(0.f, 0.f, 0.f, 0.f);
        if (xok) {
            const float4* g = reinterpret_cast<const float4*>(
                X + (size_t)(n0 + xn) * K + k0 + xk0);
#pragma unroll
            for (int j = 0; j < XNF / 4; j++) xr[j] = g[j];
        }
        float4 wr[WNF / 4];
        {
            const float4* g = reinterpret_cast<const float4*>(
                W + (size_t)wm * K + k0 + wk0);
#pragma unroll
            for (int j = 0; j < WNF / 4; j++) wr[j] = g[j];
        }
        __syncthreads();
#pragma unroll
        for (int j = 0; j < XNF / 4; j++) {
            Xs[(xk0 + 4 * j + 0) * XR + xn] = xr[j].x;
            Xs[(xk0 + 4 * j + 1) * XR + xn] = xr[j].y;
            Xs[(xk0 + 4 * j + 2) * XR + xn] = xr[j].z;
            Xs[(xk0 + 4 * j + 3) * XR + xn] = xr[j].w;
        }
#pragma unroll
        for (int j = 0; j < WNF / 4; j++) {
            Ws[(wk0 + 4 * j + 0) * WR + wm] = wr[j].x;
            Ws[(wk0 + 4 * j + 1) * WR + wm] = wr[j].y;
            Ws[(wk0 + 4 * j + 2) * WR + wm] = wr[j].z;
            Ws[(wk0 + 4 * j + 3) * WR + wm] = wr[j].w;
        }
        __syncthreads();

#pragma unroll
        for (int kk = 0; kk < 32; kk++) {
            float4 xa = *reinterpret_cast<const float4*>(&Xs[kk * XR + row0]);
            float4 xb = *reinterpret_cast<const float4*>(&Xs[kk * XR + row0 + 4]);
            float4 wa = *reinterpret_cast<const float4*>(&Ws[kk * WR + col0]);
            float4 wb = *reinterpret_cast<const float4*>(&Ws[kk * WR + col0 + CH]);
            float xv[8] = {xa.x, xa.y, xa.z, xa.w, xb.x, xb.y, xb.z, xb.w};
            float wv[8] = {wa.x, wa.y, wa.z, wa.w, wb.x, wb.y, wb.z, wb.w};
#pragma unroll
            for (int i = 0; i < 8; i++)
#pragma unroll
                for (int j = 0; j < 8; j++)
                    acc[i][j] = fmaf(xv[i], wv[j], acc[i][j]);
        }
        __syncthreads();
    }

    float bj[8];
#pragma unroll
    for (int j = 0; j < 4; j++) {
        bj[j]     = B ? B[col0 + j]      : 0.0f;
        bj[4 + j] = B ? B[col0 + CH + j] : 0.0f;
    }
#pragma unroll
    for (int i = 0; i < 8; i++) {
        int n = n0 + row0 + i;
        if (n < N) {
            if (sizeof(OT) == 2) {
                __half* Yh = reinterpret_cast<__half*>(Y);
                uint2 v0, v1;
                v0.x = h2bits(__floats2half2_rn(acc[i][0] + bj[0], acc[i][1] + bj[1]));
                v0.y = h2bits(__floats2half2_rn(acc[i][2] + bj[2], acc[i][3] + bj[3]));
                v1.x = h2bits(__floats2half2_rn(acc[i][4] + bj[4], acc[i][5] + bj[5]));
                v1.y = h2bits(__floats2half2_rn(acc[i][6] + bj[6], acc[i][7] + bj[7]));
                *reinterpret_cast<uint2*>(Yh + (size_t)n * M + col0)      = v0;
                *reinterpret_cast<uint2*>(Yh + (size_t)n * M + col0 + CH) = v1;
            } else {
                float* Yf = reinterpret_cast<float*>(Y);
                float4 v0, v1;
                v0.x = acc[i][0] + bj[0]; v0.y = acc[i][1] + bj[1];
                v0.z = acc[i][2] + bj[2]; v0.w = acc[i][3] + bj[3];
                v1.x = acc[i][4] + bj[4]; v1.y = acc[i][5] + bj[5];
                v1.z = acc[i][6] + bj[6]; v1.w = acc[i][7] + bj[7];
                *reinterpret_cast<float4*>(Yf + (size_t)n * M + col0)      = v0;
                *reinterpret_cast<float4*>(Yf + (size_t)n * M + col0 + CH) = v1;
            }
        }
    }
}

// ---------------- standalone projection kernels ----------------
__global__ void __launch_bounds__(256) proj_post_k(const float* X, const float* W, const float* B) {
    gemm3<768, 64, 256, float>(X, W, B, g_h_post, NPOST, blockIdx.x * 256);
}
__global__ void __launch_bounds__(256) proj_user_k(const float* X, const float* W, const float* B) {
    gemm3<32, 64, 256, float>(X, W, B, g_h_user, NUSER, blockIdx.x * 256);
}

// folded attention vectors; also zeroes g_smax for both layers.
__global__ void u_k(const float* __restrict__ Ws, const float* __restrict__ Wd,
                    const float* __restrict__ as_, const float* __restrict__ ad_) {
    int id = blockIdx.x * 256 + threadIdx.x;
    if (blockIdx.x == 0 && threadIdx.x < 24) g_smax[threadIdx.x] = 0u;
    if (id >= 3072) return;
    int k = id & 63, h = (id >> 6) & 1, side = (id >> 7) & 1, rl = id >> 8;
    const float* a = (side ? ad_ : as_) + (size_t)rl * 128 + h * 64;
    const float* W = (side ? Wd : Ws) + (size_t)rl * 8192 + (size_t)h * 64 * 64;
    float u = 0.0f;
#pragma unroll 8
    for (int c = 0; c < 64; c++) u = fmaf(a[c], W[c * 64 + k], u);
    g_u[id] = u;
}

// ---------------- fused stage A: hs GEMMs | al scalars (reset no longer needed) ----------------
__global__ void __launch_bounds__(256) stage_a_k(const float* __restrict__ Wsrc,
                                                 int l, int nhs) {
    int b = blockIdx.x;
    if (b < nhs) {
        int idx = 0;
#pragma unroll
        for (int r = 1; r < 5; r++) if (b >= c_HSBLK2[l][r]) idx = r;
        int rel = c_HSREL2[l][idx];
        gemm3<64, 128, 128, __half>(src_x(rel), Wsrc + ((size_t)l * 6 + rel) * 8192,
                                    nullptr, g_hs + c_HSOFF[rel], c_NSRC[rel],
                                    (b - c_HSBLK2[l][idx]) * 128);
        return;
    }
    __shared__ unsigned int s_max[12];
    if (threadIdx.x < 12) s_max[threadIdx.x] = 0u;
    __syncthreads();
    int gid = (b - nhs) * 256 + threadIdx.x;
    if (gid < c_ALN[l]) {
        int t = 0;
#pragma unroll
        for (int i = 1; i < 10; i++) if (gid >= c_ALPFX2[l][i]) t = i;
        int n = gid - c_ALPFX2[l][t];
        int rel = c_ALREL2[l][t];
        int side = c_ALSIDE2[l][t];
        const float* xr = (side ? dst_x(rel) : src_x(rel)) + (size_t)n * 64;
        const float4* x4 = reinterpret_cast<const float4*>(xr);
        const float4* u4 = reinterpret_cast<const float4*>(
            g_u + ((size_t)(l * 6 + rel) * 2 + side) * 128);
        float a0 = 0.0f, a1 = 0.0f;
#pragma unroll
        for (int k = 0; k < 16; k++) {
            float4 xv = x4[k], u0 = u4[k], u1 = u4[16 + k];
            a0 = fmaf(xv.x, u0.x, fmaf(xv.y, u0.y, fmaf(xv.z, u0.z, fmaf(xv.w, u0.w, a0))));
            a1 = fmaf(xv.x, u1.x, fmaf(xv.y, u1.y, fmaf(xv.z, u1.z, fmaf(xv.w, u1.w, a1))));
        }
        float2 r; r.x = a0; r.y = a1;
        if (side) {
            g_al_d[c_DOFF[rel] + n] = r;
        } else {
            g_al_s[c_SOFF[rel] + n] = r;
            atomicMax(&s_max[rel * 2 + 0], encf(a0));
            atomicMax(&s_max[rel * 2 + 1], encf(a1));
        }
    }
    __syncthreads();
    if (threadIdx.x < 12 && s_max[threadIdx.x] != 0u)
        atomicMax(&g_smax[l * 12 + threadIdx.x], s_max[threadIdx.x]);
}

// ---------------- CSR pull aggregation: one warp per dst node, zero atomics ----------------
// Single pass: softmax numerators (stable via per-rel src-max upper bound),
// denominators and messages accumulated in registers; per-relation rescale;
// relations + biases summed; relu folded (layer 0) / raw to acc (layer 1).
__global__ void __launch_bounds__(256) csr_agg_k(const float* __restrict__ gb, int l) {
    int gw = (blockIdx.x * 256 + threadIdx.x) >> 5;
    int lane = threadIdx.x & 31;
    int nw = (l == 0) ? (NPOST + NUSER) : NPOST;
    if (gw >= nw) return;
    bool isuser = (gw >= NPOST);
    int d = isuser ? gw - NPOST : gw;
    int nrel = isuser ? 2 : 3;

    float t0 = 0.0f, t1 = 0.0f;
    const float* bb = gb + l * 384;

    for (int ri = 0; ri < nrel; ri++) {
        int rel = isuser ? c_UREL[ri] : c_PREL[ri];
        int base = c_DOFF[rel] + d;
        int st = g_off[base];
        int n  = g_cnt[base];
        float2 ad = g_al_d[base];
        float m0 = lrelu(decf(g_smax[l * 12 + rel * 2 + 0]) + ad.x);
        float m1 = lrelu(decf(g_smax[l * 12 + rel * 2 + 1]) + ad.y);
        const __half* hsr = g_hs + c_HSOFF[rel];
        const float2* als = g_al_s + c_SOFF[rel];
        float ss0 = 0.0f, ss1 = 0.0f;
        float a00 = 0.0f, a01 = 0.0f, a10 = 0.0f, a11 = 0.0f;
        for (int j = st; j < st + n; j++) {
            int s = g_csr_src[j];
            float2 as = als[s];
            float p0 = __expf(lrelu(as.x + ad.x) - m0);
            float p1 = __expf(lrelu(as.y + ad.y) - m1);
            ss0 += p0; ss1 += p1;
            const __half* row = hsr + (size_t)s * 128;
            float2 f0 = __half22float2(*reinterpret_cast<const __half2*>(row + lane * 2));
            float2 f1 = __half22float2(*reinterpret_cast<const __half2*>(row + 64 + lane * 2));
            a00 = fmaf(p0, f0.x, a00); a01 = fmaf(p0, f0.y, a01);
            a10 = fmaf(p1, f1.x, a10); a11 = fmaf(p1, f1.y, a11);
        }
        float i0 = 0.5f / (ss0 + 1e-16f);
        float i1 = 0.5f / (ss1 + 1e-16f);
        t0 += a00 * i0 + a10 * i1;
        t1 += a01 * i0 + a11 * i1;
        t0 += bb[rel * 64 + lane * 2 + 0];
        t1 += bb[rel * 64 + lane * 2 + 1];
    }

    float2 o;
    if (l == 0) {
        o.x = fmaxf(t0, 0.0f); o.y = fmaxf(t1, 0.0f);
        float* dst = isuser ? g_h_user : g_h_post;
        *reinterpret_cast<float2*>(dst + (size_t)d * 64 + lane * 2) = o;
    } else {
        o.x = t0; o.y = t1;
        *reinterpret_cast<float2*>(g_acc_post + (size_t)d * 64 + lane * 2) = o;
    }
}

// classifier: one warp per post node; layer-2 relu folded into the load
__global__ void __launch_bounds__(256) cls_k(const float* __restrict__ w1,
                                             const float* __restrict__ b1,
                                             const float* __restrict__ w2,
                                             const float* __restrict__ b2,
                                             float* __restrict__ out) {
    int gid = blockIdx.x * 256 + threadIdx.x;
    int n = gid >> 5, lane = gid & 31;
    if (n >= NPOST) return;
    const float4* x4 = reinterpret_cast<const float4*>(g_acc_post + (size_t)n * 64);
    const float4* w4 = reinterpret_cast<const float4*>(w1 + (size_t)lane * 64);
    float a = 0.0f;
#pragma unroll
    for (int k = 0; k < 16; k++) {
        float4 xv = x4[k], wv = w4[k];
        xv.x = fmaxf(xv.x, 0.0f); xv.y = fmaxf(xv.y, 0.0f);
        xv.z = fmaxf(xv.z, 0.0f); xv.w = fmaxf(xv.w, 0.0f);
        a = fmaf(xv.x, wv.x, fmaf(xv.y, wv.y, fmaf(xv.z, wv.z, fmaf(xv.w, wv.w, a))));
    }
    float h = fmaxf(a + b1[lane], 0.0f) * w2[lane];
#pragma unroll
    for (int off = 16; off > 0; off >>= 1)
        h += __shfl_xor_sync(0xffffffffu, h, off);
    if (lane == 0) out[n] = h + b2[0];
}

// ---------------- launch ----------------
extern "C" void kernel_launch(void* const* d_in, const int* in_sizes, int n_in,
                              void* d_out, int out_size) {
    const float* x_post = (const float*)d_in[0];
    const float* x_user = (const float*)d_in[1];
    EdgeParams ep;
    for (int r = 0; r < 6; r++) {
        ep.src[r] = (const int*)d_in[3 + 2 * r];
        ep.dst[r] = (const int*)d_in[4 + 2 * r];
    }
    const float* post_w = (const float*)d_in[15];
    const float* post_b = (const float*)d_in[16];
    const float* user_w = (const float*)d_in[17];
    const float* user_b = (const float*)d_in[18];
    const float* W_src  = (const float*)d_in[21];
    const float* W_dst  = (const float*)d_in[22];
    const float* a_src  = (const float*)d_in[23];
    const float* a_dst  = (const float*)d_in[24];
    const float* gat_b  = (const float*)d_in[25];
    const float* cls_w1 = (const float*)d_in[26];
    const float* cls_b1 = (const float*)d_in[27];
    const float* cls_w2 = (const float*)d_in[28];
    const float* cls_b2 = (const float*)d_in[29];
    float* out = (float*)d_out;

    // CSR build (graph static across launch; edges only)
    zero_cnt_k<<<1641, 256>>>();
    hist_k<<<5274, 256>>>(ep);
    scan1_k<<<103, 512>>>();
    scan2_k<<<1, 32>>>(103);
    scan3_k<<<1641, 256>>>();
    scatter_k<<<5274, 256>>>(ep);

    proj_post_k<<<391, 256>>>(x_post, post_w, post_b);
    proj_user_k<<<196, 256>>>(x_user, user_w, user_b);
    u_k<<<12, 256>>>(W_src, W_dst, a_src, a_dst);

    // layer 0: rels {0,1,3,4,5}
    stage_a_k<<<2346 + 2735, 256>>>(W_src, 0, 2346);
    csr_agg_k<<<18750, 256>>>(gat_b, 0);

    // layer 1: rels {0,1,5}
    stage_a_k<<<1564 + 1954, 256>>>(W_src, 1, 1564);
    csr_agg_k<<<12500, 256>>>(gat_b, 1);

    cls_k<<<12500, 256>>>(cls_w1, cls_b1, cls_w2, cls_b2, out);
}

// round 17
// speedup vs baseline: 3.6275x; 1.1878x over previous
#include <cuda_runtime.h>
#include <cuda_bf16.h>
#include <cuda_fp16.h>
#include <cstdint>

#define NPOST 100000
#define NUSER 50000
#define NSRC_TOT 400000
#define NDST_TOT 420000
#define NEDGE_LIVE 1350000
#define BIG (1 << 29)

// ---------------- static device scratch ----------------
__device__ float g_h_post[NPOST * 64];
__device__ float g_h_user[NUSER * 64];
__device__ float g_acc_post[NPOST * 64];
__device__ __half g_hs[51200000];       // concat per-relation hs [N_src][128], fp16
__device__ float2 g_al_s[NSRC_TOT];
__device__ float2 g_al_d[NDST_TOT];
__device__ float g_u[3072];             // folded attention vectors [l][r][side][h][64]
__device__ unsigned int g_smax[24];     // encoded per-(layer,rel,head) max of al_s
// CSR (built once per launch; graph is static)
__device__ int g_cnt[NDST_TOT];
__device__ int g_off[NDST_TOT];
__device__ int g_fill[NDST_TOT];
__device__ int g_bsum[128];
__device__ int g_csr_src[NEDGE_LIVE];

// ---------------- constant tables ----------------
__constant__ int c_SOFF[6]  = {0, 50000, 100000, 200000, 250000, 300000};
__constant__ int c_DOFF[6]  = {0, 100000, 200000, 220000, 270000, 320000};
__constant__ int c_HSOFF[6] = {0, 6400000, 12800000, 25600000, 32000000, 38400000};
__constant__ int c_NSRC[6]  = {50000, 50000, 100000, 50000, 50000, 100000};

// per-layer live-relation dispatch (ent + rel2 dead; layer1 post rels only)
__constant__ int c_HSBLK2[2][5] = {{0, 391, 782, 1173, 1564},
                                   {0, 391, 782, BIG, BIG}};
__constant__ int c_HSREL2[2][5] = {{0, 1, 3, 4, 5}, {0, 1, 5, 5, 5}};
__constant__ int c_ALPFX2[2][10] = {
    {0, 50000, 100000, 150000, 200000, 300000, 400000, 500000, 550000, 600000},
    {0, 50000, 100000, 200000, 300000, 400000, BIG, BIG, BIG, BIG}};
__constant__ int c_ALREL2[2][10] = {{0, 1, 3, 4, 5, 0, 1, 3, 4, 5},
                                    {0, 1, 5, 0, 1, 5, 5, 5, 5, 5}};
__constant__ int c_ALSIDE2[2][10] = {{0, 0, 0, 0, 0, 1, 1, 1, 1, 1},
                                     {0, 0, 0, 1, 1, 1, 1, 1, 1, 1}};
__constant__ int c_ALN[2] = {700000, 500000};
// live-edge dispatch (all live edges; used for CSR build)
__constant__ int c_EPFX[5] = {0, 100000, 300000, 700000, 1100000};
__constant__ int c_EREL[5] = {0, 1, 3, 4, 5};
__constant__ int c_PREL[3] = {0, 1, 5};   // post-dst relations
__constant__ int c_UREL[2] = {3, 4};      // user-dst relations

struct EdgeParams { const int* src[6]; const int* dst[6]; };

// ---------------- helpers ----------------
__device__ __forceinline__ const float* src_x(int rel) {
    return (rel == 5) ? g_h_post : g_h_user;
}
__device__ __forceinline__ const float* dst_x(int rel) {
    return (rel == 3 || rel == 4) ? g_h_user : g_h_post;
}
__device__ __forceinline__ float lrelu(float x) { return x > 0.0f ? x : 0.2f * x; }
__device__ __forceinline__ unsigned int encf(float f) {
    unsigned int u = __float_as_uint(f);
    return (u & 0x80000000u) ? ~u : (u | 0x80000000u);
}
__device__ __forceinline__ float decf(unsigned int u) {
    return (u & 0x80000000u) ? __uint_as_float(u & 0x7fffffffu) : __uint_as_float(~u);
}
__device__ __forceinline__ unsigned int h2bits(__half2 h) {
    return *reinterpret_cast<unsigned int*>(&h);
}
__device__ __forceinline__ unsigned int f2tf32(float f) {
    unsigned int r;
    asm("cvt.rna.tf32.f32 %0, %1;" : "=r"(r) : "f"(f));
    return r;
}
__device__ __forceinline__ void mma_tf32(float c[4],
                                         unsigned a0, unsigned a1,
                                         unsigned a2, unsigned a3,
                                         unsigned b0, unsigned b1) {
    asm volatile(
        "mma.sync.aligned.m16n8k8.row.col.f32.tf32.tf32.f32 "
        "{%0,%1,%2,%3}, {%4,%5,%6,%7}, {%8,%9}, {%0,%1,%2,%3};"
        : "+f"(c[0]), "+f"(c[1]), "+f"(c[2]), "+f"(c[3])
        : "r"(a0), "r"(a1), "r"(a2), "r"(a3), "r"(b0), "r"(b1));
}

// ---------------- CSR build (once per launch) ----------------
__global__ void zero_cnt_k() {
    int i = blockIdx.x * 256 + threadIdx.x;
    if (i < NDST_TOT) g_cnt[i] = 0;
}
__global__ void hist_k(EdgeParams p) {
    int gid = blockIdx.x * 256 + threadIdx.x;
    if (gid >= NEDGE_LIVE) return;
    int idx = 0;
#pragma unroll
    for (int r = 1; r < 5; r++) if (gid >= c_EPFX[r]) idx = r;
    int rel = c_EREL[idx];
    int e = gid - c_EPFX[idx];
    atomicAdd(&g_cnt[c_DOFF[rel] + p.dst[rel][e]], 1);
}
__global__ void scan1_k() {
    __shared__ int sm[512];
    int b = blockIdx.x, t = threadIdx.x;
    int base = b * 4096 + t * 8;
    int v[8], s = 0;
#pragma unroll
    for (int i = 0; i < 8; i++) {
        int idx = base + i;
        v[i] = (idx < NDST_TOT) ? g_cnt[idx] : 0;
        s += v[i];
    }
    sm[t] = s;
    __syncthreads();
    for (int o = 1; o < 512; o <<= 1) {
        int x = (t >= o) ? sm[t - o] : 0;
        __syncthreads();
        sm[t] += x;
        __syncthreads();
    }
    int run = sm[t] - s;
    if (t == 511) g_bsum[b] = sm[511];
#pragma unroll
    for (int i = 0; i < 8; i++) {
        int idx = base + i;
        if (idx < NDST_TOT) g_off[idx] = run;
        run += v[i];
    }
}
__global__ void scan2_k(int nb) {
    if (threadIdx.x == 0 && blockIdx.x == 0) {
        int run = 0;
        for (int i = 0; i < nb; i++) { int t = g_bsum[i]; g_bsum[i] = run; run += t; }
    }
}
__global__ void scan3_k() {
    int i = blockIdx.x * 256 + threadIdx.x;
    if (i >= NDST_TOT) return;
    int o = g_off[i] + g_bsum[i >> 12];
    g_off[i] = o;
    g_fill[i] = o;
}
__global__ void scatter_k(EdgeParams p) {
    int gid = blockIdx.x * 256 + threadIdx.x;
    if (gid >= NEDGE_LIVE) return;
    int idx = 0;
#pragma unroll
    for (int r = 1; r < 5; r++) if (gid >= c_EPFX[r]) idx = r;
    int rel = c_EREL[idx];
    int e = gid - c_EPFX[idx];
    int pos = atomicAdd(&g_fill[c_DOFF[rel] + p.dst[rel][e]], 1);
    g_csr_src[pos] = p.src[rel][e];
}

// ---------------- tensor-core proj_post: h_post = x_post @ W^T + b (tf32) ----------------
// CTA: 256 thr / 8 warps; tile 128 rows x 64 cols; K=768 in 32-slabs.
// Warp w: rows w*16..+15, all 64 cols. Fragment smem pitch 36 -> banks 4g+tg
// (conflict-free). fp32 accumulate; tf32 inputs (~1e-4 rel on h_post).
__global__ void __launch_bounds__(256) proj_post_tc_k(const float* __restrict__ X,
                                                      const float* __restrict__ W,
                                                      const float* __restrict__ B) {
    __shared__ unsigned int Xs[128][36];
    __shared__ unsigned int Ws[64][36];
    const int t = threadIdx.x;
    const int n0 = blockIdx.x * 128;
    const int lane = t & 31, w = t >> 5;
    const int g = lane >> 2, tg = lane & 3;
    const int row0 = w * 16;

    const int sxr = t >> 1, sxk = (t & 1) * 16;   // X staging: 16 floats/thread
    const int swc = t >> 2, swk = (t & 3) * 8;    // W staging: 8 floats/thread
    const bool xok = (n0 + sxr) < NPOST;

    float c[8][4];
#pragma unroll
    for (int i = 0; i < 8; i++)
#pragma unroll
        for (int j = 0; j < 4; j++) c[i][j] = 0.0f;

    for (int k0 = 0; k0 < 768; k0 += 32) {
        float4 xr[4];
#pragma unroll
        for (int j = 0; j < 4; j++) xr[j] = make_float4(0.f, 0.f, 0.f, 0.f);
        if (xok) {
            const float4* gp = reinterpret_cast<const float4*>(
                X + (size_t)(n0 + sxr) * 768 + k0 + sxk);
#pragma unroll
            for (int j = 0; j < 4; j++) xr[j] = gp[j];
        }
        float4 wr[2];
        {
            const float4* gp = reinterpret_cast<const float4*>(
                W + (size_t)swc * 768 + k0 + swk);
            wr[0] = gp[0]; wr[1] = gp[1];
        }
        __syncthreads();   // previous slab fully consumed
#pragma unroll
        for (int j = 0; j < 4; j++) {
            uint4 u;
            u.x = f2tf32(xr[j].x); u.y = f2tf32(xr[j].y);
            u.z = f2tf32(xr[j].z); u.w = f2tf32(xr[j].w);
            *reinterpret_cast<uint4*>(&Xs[sxr][sxk + 4 * j]) = u;
        }
#pragma unroll
        for (int j = 0; j < 2; j++) {
            uint4 u;
            u.x = f2tf32(wr[j].x); u.y = f2tf32(wr[j].y);
            u.z = f2tf32(wr[j].z); u.w = f2tf32(wr[j].w);
            *reinterpret_cast<uint4*>(&Ws[swc][swk + 4 * j]) = u;
        }
        __syncthreads();

#pragma unroll
        for (int ks = 0; ks < 4; ks++) {
            int kk = ks * 8;
            unsigned a0 = Xs[row0 + g][kk + tg];
            unsigned a1 = Xs[row0 + g + 8][kk + tg];
            unsigned a2 = Xs[row0 + g][kk + tg + 4];
            unsigned a3 = Xs[row0 + g + 8][kk + tg + 4];
#pragma unroll
            for (int nc = 0; nc < 8; nc++) {
                unsigned b0 = Ws[nc * 8 + g][kk + tg];
                unsigned b1 = Ws[nc * 8 + g][kk + tg + 4];
                mma_tf32(c[nc], a0, a1, a2, a3, b0, b1);
            }
        }
    }

    int r0 = n0 + row0 + g, r1 = r0 + 8;
#pragma unroll
    for (int nc = 0; nc < 8; nc++) {
        int col = nc * 8 + tg * 2;
        float b0v = B[col], b1v = B[col + 1];
        if (r0 < NPOST) {
            float2 v; v.x = c[nc][0] + b0v; v.y = c[nc][1] + b1v;
            *reinterpret_cast<float2*>(g_h_post + (size_t)r0 * 64 + col) = v;
        }
        if (r1 < NPOST) {
            float2 v; v.x = c[nc][2] + b0v; v.y = c[nc][3] + b1v;
            *reinterpret_cast<float2*>(g_h_post + (size_t)r1 * 64 + col) = v;
        }
    }
}

// ---------------- 8x8-tile scalar GEMM (proj_user + hs; fp32 accum) ----------------
template <int K, int M, int ROWS, typename OT>
__device__ __forceinline__ void gemm3(const float* __restrict__ X,
                                      const float* __restrict__ W,
                                      const float* __restrict__ B,
                                      OT* __restrict__ Y, int N, int n0)
{
    constexpr int XR = ROWS + 4;
    constexpr int WR = M + 4;
    constexpr int CG = M / 8;
    constexpr int CH = M / 2;
    constexpr int XNF = (ROWS == 256) ? 32 : 16;
    constexpr int WNF = (M == 64) ? 8 : 16;
    __shared__ float Xs[32 * XR];
    __shared__ float Ws[32 * WR];

    const int t = threadIdx.x;
    const int cg = t % CG, rg = t / CG;
    const int col0 = cg * 4;
    const int row0 = rg * 8;

    const int xn  = (ROWS == 256) ? t : (t & 127);
    const int xk0 = (ROWS == 256) ? 0 : ((t >> 7) * 16);
    const int wm  = (M == 64) ? (t & 63) : (t & 127);
    const int wk0 = (M == 64) ? ((t >> 6) * 8) : ((t >> 7) * 16);

    float acc[8][8];
#pragma unroll
    for (int i = 0; i < 8; i++)
#pragma unroll
        for (int j = 0; j < 8; j++) acc[i][j] = 0.0f;

    const bool xok = (n0 + xn) < N;

    for (int k0 = 0; k0 < K; k0 += 32) {
        float4 xr[XNF / 4];
#pragma unroll
        for (int j = 0; j < XNF / 4; j++) xr[j] = make_float4(0.f, 0.f, 0.f, 0.f);
        if (xok) {
            const float4* g = reinterpret_cast<const float4*>(
                X + (size_t)(n0 + xn) * K + k0 + xk0);
#pragma unroll
            for (int j = 0; j < XNF / 4; j++) xr[j] = g[j];
        }
        float4 wr[WNF / 4];
        {
            const float4* g = reinterpret_cast<const float4*>(
                W + (size_t)wm * K + k0 + wk0);
#pragma unroll
            for (int j = 0; j < WNF / 4; j++) wr[j] = g[j];
        }
        __syncthreads();
#pragma unroll
        for (int j = 0; j < XNF / 4; j++) {
            Xs[(xk0 + 4 * j + 0) * XR + xn] = xr[j].x;
            Xs[(xk0 + 4 * j + 1) * XR + xn] = xr[j].y;
            Xs[(xk0 + 4 * j + 2) * XR + xn] = xr[j].z;
            Xs[(xk0 + 4 * j + 3) * XR + xn] = xr[j].w;
        }
#pragma unroll
        for (int j = 0; j < WNF / 4; j++) {
            Ws[(wk0 + 4 * j + 0) * WR + wm] = wr[j].x;
            Ws[(wk0 + 4 * j + 1) * WR + wm] = wr[j].y;
            Ws[(wk0 + 4 * j + 2) * WR + wm] = wr[j].z;
            Ws[(wk0 + 4 * j + 3) * WR + wm] = wr[j].w;
        }
        __syncthreads();

#pragma unroll
        for (int kk = 0; kk < 32; kk++) {
            float4 xa = *reinterpret_cast<const float4*>(&Xs[kk * XR + row0]);
            float4 xb = *reinterpret_cast<const float4*>(&Xs[kk * XR + row0 + 4]);
            float4 wa = *reinterpret_cast<const float4*>(&Ws[kk * WR + col0]);
            float4 wb = *reinterpret_cast<const float4*>(&Ws[kk * WR + col0 + CH]);
            float xv[8] = {xa.x, xa.y, xa.z, xa.w, xb.x, xb.y, xb.z, xb.w};
            float wv[8] = {wa.x, wa.y, wa.z, wa.w, wb.x, wb.y, wb.z, wb.w};
#pragma unroll
            for (int i = 0; i < 8; i++)
#pragma unroll
                for (int j = 0; j < 8; j++)
                    acc[i][j] = fmaf(xv[i], wv[j], acc[i][j]);
        }
        __syncthreads();
    }

    float bj[8];
#pragma unroll
    for (int j = 0; j < 4; j++) {
        bj[j]     = B ? B[col0 + j]      : 0.0f;
        bj[4 + j] = B ? B[col0 + CH + j] : 0.0f;
    }
#pragma unroll
    for (int i = 0; i < 8; i++) {
        int n = n0 + row0 + i;
        if (n < N) {
            if (sizeof(OT) == 2) {
                __half* Yh = reinterpret_cast<__half*>(Y);
                uint2 v0, v1;
                v0.x = h2bits(__floats2half2_rn(acc[i][0] + bj[0], acc[i][1] + bj[1]));
                v0.y = h2bits(__floats2half2_rn(acc[i][2] + bj[2], acc[i][3] + bj[3]));
                v1.x = h2bits(__floats2half2_rn(acc[i][4] + bj[4], acc[i][5] + bj[5]));
                v1.y = h2bits(__floats2half2_rn(acc[i][6] + bj[6], acc[i][7] + bj[7]));
                *reinterpret_cast<uint2*>(Yh + (size_t)n * M + col0)      = v0;
                *reinterpret_cast<uint2*>(Yh + (size_t)n * M + col0 + CH) = v1;
            } else {
                float* Yf = reinterpret_cast<float*>(Y);
                float4 v0, v1;
                v0.x = acc[i][0] + bj[0]; v0.y = acc[i][1] + bj[1];
                v0.z = acc[i][2] + bj[2]; v0.w = acc[i][3] + bj[3];
                v1.x = acc[i][4] + bj[4]; v1.y = acc[i][5] + bj[5];
                v1.z = acc[i][6] + bj[6]; v1.w = acc[i][7] + bj[7];
                *reinterpret_cast<float4*>(Yf + (size_t)n * M + col0)      = v0;
                *reinterpret_cast<float4*>(Yf + (size_t)n * M + col0 + CH) = v1;
            }
        }
    }
}

__global__ void __launch_bounds__(256) proj_user_k(const float* X, const float* W, const float* B) {
    gemm3<32, 64, 256, float>(X, W, B, g_h_user, NUSER, blockIdx.x * 256);
}

// folded attention vectors; also zeroes g_smax for both layers.
__global__ void u_k(const float* __restrict__ Ws, const float* __restrict__ Wd,
                    const float* __restrict__ as_, const float* __restrict__ ad_) {
    int id = blockIdx.x * 256 + threadIdx.x;
    if (blockIdx.x == 0 && threadIdx.x < 24) g_smax[threadIdx.x] = 0u;
    if (id >= 3072) return;
    int k = id & 63, h = (id >> 6) & 1, side = (id >> 7) & 1, rl = id >> 8;
    const float* a = (side ? ad_ : as_) + (size_t)rl * 128 + h * 64;
    const float* W = (side ? Wd : Ws) + (size_t)rl * 8192 + (size_t)h * 64 * 64;
    float u = 0.0f;
#pragma unroll 8
    for (int c = 0; c < 64; c++) u = fmaf(a[c], W[c * 64 + k], u);
    g_u[id] = u;
}

// ---------------- fused stage A: hs GEMMs | al scalars ----------------
__global__ void __launch_bounds__(256) stage_a_k(const float* __restrict__ Wsrc,
                                                 int l, int nhs) {
    int b = blockIdx.x;
    if (b < nhs) {
        int idx = 0;
#pragma unroll
        for (int r = 1; r < 5; r++) if (b >= c_HSBLK2[l][r]) idx = r;
        int rel = c_HSREL2[l][idx];
        gemm3<64, 128, 128, __half>(src_x(rel), Wsrc + ((size_t)l * 6 + rel) * 8192,
                                    nullptr, g_hs + c_HSOFF[rel], c_NSRC[rel],
                                    (b - c_HSBLK2[l][idx]) * 128);
        return;
    }
    __shared__ unsigned int s_max[12];
    if (threadIdx.x < 12) s_max[threadIdx.x] = 0u;
    __syncthreads();
    int gid = (b - nhs) * 256 + threadIdx.x;
    if (gid < c_ALN[l]) {
        int t = 0;
#pragma unroll
        for (int i = 1; i < 10; i++) if (gid >= c_ALPFX2[l][i]) t = i;
        int n = gid - c_ALPFX2[l][t];
        int rel = c_ALREL2[l][t];
        int side = c_ALSIDE2[l][t];
        const float* xr = (side ? dst_x(rel) : src_x(rel)) + (size_t)n * 64;
        const float4* x4 = reinterpret_cast<const float4*>(xr);
        const float4* u4 = reinterpret_cast<const float4*>(
            g_u + ((size_t)(l * 6 + rel) * 2 + side) * 128);
        float a0 = 0.0f, a1 = 0.0f;
#pragma unroll
        for (int k = 0; k < 16; k++) {
            float4 xv = x4[k], u0 = u4[k], u1 = u4[16 + k];
            a0 = fmaf(xv.x, u0.x, fmaf(xv.y, u0.y, fmaf(xv.z, u0.z, fmaf(xv.w, u0.w, a0))));
            a1 = fmaf(xv.x, u1.x, fmaf(xv.y, u1.y, fmaf(xv.z, u1.z, fmaf(xv.w, u1.w, a1))));
        }
        float2 r; r.x = a0; r.y = a1;
        if (side) {
            g_al_d[c_DOFF[rel] + n] = r;
        } else {
            g_al_s[c_SOFF[rel] + n] = r;
            atomicMax(&s_max[rel * 2 + 0], encf(a0));
            atomicMax(&s_max[rel * 2 + 1], encf(a1));
        }
    }
    __syncthreads();
    if (threadIdx.x < 12 && s_max[threadIdx.x] != 0u)
        atomicMax(&g_smax[l * 12 + threadIdx.x], s_max[threadIdx.x]);
}

// ---------------- CSR pull aggregation: one warp per dst node, zero atomics ----------------
__global__ void __launch_bounds__(256) csr_agg_k(const float* __restrict__ gb, int l) {
    int gw = (blockIdx.x * 256 + threadIdx.x) >> 5;
    int lane = threadIdx.x & 31;
    int nw = (l == 0) ? (NPOST + NUSER) : NPOST;
    if (gw >= nw) return;
    bool isuser = (gw >= NPOST);
    int d = isuser ? gw - NPOST : gw;
    int nrel = isuser ? 2 : 3;

    float t0 = 0.0f, t1 = 0.0f;
    const float* bb = gb + l * 384;

    for (int ri = 0; ri < nrel; ri++) {
        int rel = isuser ? c_UREL[ri] : c_PREL[ri];
        int base = c_DOFF[rel] + d;
        int st = g_off[base];
        int n  = g_cnt[base];
        float2 ad = g_al_d[base];
        float m0 = lrelu(decf(g_smax[l * 12 + rel * 2 + 0]) + ad.x);
        float m1 = lrelu(decf(g_smax[l * 12 + rel * 2 + 1]) + ad.y);
        const __half* hsr = g_hs + c_HSOFF[rel];
        const float2* als = g_al_s + c_SOFF[rel];
        float ss0 = 0.0f, ss1 = 0.0f;
        float a00 = 0.0f, a01 = 0.0f, a10 = 0.0f, a11 = 0.0f;
        for (int j = st; j < st + n; j++) {
            int s = g_csr_src[j];
            float2 as = als[s];
            float p0 = __expf(lrelu(as.x + ad.x) - m0);
            float p1 = __expf(lrelu(as.y + ad.y) - m1);
            ss0 += p0; ss1 += p1;
            const __half* row = hsr + (size_t)s * 128;
            float2 f0 = __half22float2(*reinterpret_cast<const __half2*>(row + lane * 2));
            float2 f1 = __half22float2(*reinterpret_cast<const __half2*>(row + 64 + lane * 2));
            a00 = fmaf(p0, f0.x, a00); a01 = fmaf(p0, f0.y, a01);
            a10 = fmaf(p1, f1.x, a10); a11 = fmaf(p1, f1.y, a11);
        }
        float i0 = 0.5f / (ss0 + 1e-16f);
        float i1 = 0.5f / (ss1 + 1e-16f);
        t0 += a00 * i0 + a10 * i1;
        t1 += a01 * i0 + a11 * i1;
        t0 += bb[rel * 64 + lane * 2 + 0];
        t1 += bb[rel * 64 + lane * 2 + 1];
    }

    float2 o;
    if (l == 0) {
        o.x = fmaxf(t0, 0.0f); o.y = fmaxf(t1, 0.0f);
        float* dst = isuser ? g_h_user : g_h_post;
        *reinterpret_cast<float2*>(dst + (size_t)d * 64 + lane * 2) = o;
    } else {
        o.x = t0; o.y = t1;
        *reinterpret_cast<float2*>(g_acc_post + (size_t)d * 64 + lane * 2) = o;
    }
}

// classifier: one warp per post node; layer-2 relu folded into the load
__global__ void __launch_bounds__(256) cls_k(const float* __restrict__ w1,
                                             const float* __restrict__ b1,
                                             const float* __restrict__ w2,
                                             const float* __restrict__ b2,
                                             float* __restrict__ out) {
    int gid = blockIdx.x * 256 + threadIdx.x;
    int n = gid >> 5, lane = gid & 31;
    if (n >= NPOST) return;
    const float4* x4 = reinterpret_cast<const float4*>(g_acc_post + (size_t)n * 64);
    const float4* w4 = reinterpret_cast<const float4*>(w1 + (size_t)lane * 64);
    float a = 0.0f;
#pragma unroll
    for (int k = 0; k < 16; k++) {
        float4 xv = x4[k], wv = w4[k];
        xv.x = fmaxf(xv.x, 0.0f); xv.y = fmaxf(xv.y, 0.0f);
        xv.z = fmaxf(xv.z, 0.0f); xv.w = fmaxf(xv.w, 0.0f);
        a = fmaf(xv.x, wv.x, fmaf(xv.y, wv.y, fmaf(xv.z, wv.z, fmaf(xv.w, wv.w, a))));
    }
    float h = fmaxf(a + b1[lane], 0.0f) * w2[lane];
#pragma unroll
    for (int off = 16; off > 0; off >>= 1)
        h += __shfl_xor_sync(0xffffffffu, h, off);
    if (lane == 0) out[n] = h + b2[0];
}

// ---------------- launch ----------------
extern "C" void kernel_launch(void* const* d_in, const int* in_sizes, int n_in,
                              void* d_out, int out_size) {
    const float* x_post = (const float*)d_in[0];
    const float* x_user = (const float*)d_in[1];
    EdgeParams ep;
    for (int r = 0; r < 6; r++) {
        ep.src[r] = (const int*)d_in[3 + 2 * r];
        ep.dst[r] = (const int*)d_in[4 + 2 * r];
    }
    const float* post_w = (const float*)d_in[15];
    const float* post_b = (const float*)d_in[16];
    const float* user_w = (const float*)d_in[17];
    const float* user_b = (const float*)d_in[18];
    const float* W_src  = (const float*)d_in[21];
    const float* W_dst  = (const float*)d_in[22];
    const float* a_src  = (const float*)d_in[23];
    const float* a_dst  = (const float*)d_in[24];
    const float* gat_b  = (const float*)d_in[25];
    const float* cls_w1 = (const float*)d_in[26];
    const float* cls_b1 = (const float*)d_in[27];
    const float* cls_w2 = (const float*)d_in[28];
    const float* cls_b2 = (const float*)d_in[29];
    float* out = (float*)d_out;

    // CSR build (graph static across launch; edges only)
    zero_cnt_k<<<1641, 256>>>();
    hist_k<<<5274, 256>>>(ep);
    scan1_k<<<103, 512>>>();
    scan2_k<<<1, 32>>>(103);
    scan3_k<<<1641, 256>>>();
    scatter_k<<<5274, 256>>>(ep);

    proj_post_tc_k<<<782, 256>>>(x_post, post_w, post_b);
    proj_user_k<<<196, 256>>>(x_user, user_w, user_b);
    u_k<<<12, 256>>>(W_src, W_dst, a_src, a_dst);

    // layer 0: rels {0,1,3,4,5}
    stage_a_k<<<2346 + 2735, 256>>>(W_src, 0, 2346);
    csr_agg_k<<<18750, 256>>>(gat_b, 0);

    // layer 1: rels {0,1,5}
    stage_a_k<<<1564 + 1954, 256>>>(W_src, 1, 1564);
    csr_agg_k<<<12500, 256>>>(gat_b, 1);

    cls_k<<<12500, 256>>>(cls_w1, cls_b1, cls_w2, cls_b2, out);
}